// round 4
// baseline (speedup 1.0000x reference)
#include <cuda_runtime.h>
#include <cuda_bf16.h>
#include <cstdint>

#define NNODES  50000
#define HID     128
#define INDIM   768
#define NGRAPH  128
#define NCLS    3

// ---------------- scratch (static device globals; no allocation) ----------
__device__ float g_h   [NNODES * HID];   // h0 -> h1 -> h2
__device__ float g_hs  [NNODES * HID];   // dinv-scaled matmul output
__device__ float g_agg [NNODES * HID];   // edge aggregation target
__device__ float g_dinv[NNODES];
__device__ int   g_deg [NNODES];
__device__ float g_pool[NGRAPH * HID + NGRAPH];  // sums + counts

// ---------------- small PTX helpers ---------------------------------------
__device__ __forceinline__ unsigned long long pk2(float x) {
    unsigned long long r;
    asm("mov.b64 %0, {%1, %1};" : "=l"(r) : "f"(x));
    return r;
}
__device__ __forceinline__ void upk(unsigned long long p, float &x, float &y) {
    asm("mov.b64 {%0, %1}, %2;" : "=f"(x), "=f"(y) : "l"(p));
}
__device__ __forceinline__ void fma2(unsigned long long &d, unsigned long long a,
                                     unsigned long long b) {
    asm("fma.rn.f32x2 %0, %1, %2, %0;" : "+l"(d) : "l"(a), "l"(b));
}
__device__ __forceinline__ void red4(float *p, float4 v) {
    asm volatile("red.global.add.v4.f32 [%0], {%1, %2, %3, %4};"
                 :: "l"(p), "f"(v.x), "f"(v.y), "f"(v.z), "f"(v.w) : "memory");
}

// ---------------- zero fill (graph memset nodes can't touch __device__) ---
__global__ void k_zero4(float4 *__restrict__ p, int n4) {
    int i = blockIdx.x * blockDim.x + threadIdx.x;
    if (i < n4) p[i] = make_float4(0.f, 0.f, 0.f, 0.f);
}
__global__ void k_zero_deg(int *__restrict__ p, int n) {
    int i = blockIdx.x * blockDim.x + threadIdx.x;
    if (i < n) p[i] = 0;
}

// ---------------- degree / dinv -------------------------------------------
__global__ void k_deg(const int *__restrict__ ei, int E) {
    int i = blockIdx.x * blockDim.x + threadIdx.x;
    if (i < E) atomicAdd(&g_deg[ei[E + i]], 1);
}
__global__ void k_dinv(int N) {
    int i = blockIdx.x * blockDim.x + threadIdx.x;
    if (i < N) g_dinv[i] = rsqrtf((float)g_deg[i] + 1.0f);
}

// ---------------- GEMM: C[M,128] = A[M,K] @ B[K,128]  (+bias | *dinv) -----
// BM=64, BN=128 (full), BK=16; 256 threads; 4x8 outputs/thread via f32x2.
__global__ void __launch_bounds__(256)
gemm128(const float *__restrict__ A, const float *__restrict__ B,
        const float *__restrict__ bias, const float *__restrict__ dinv,
        float *__restrict__ C, int M, int K)
{
    __shared__ float As[16][68];    // [k][m], padded (16B-aligned stride)
    __shared__ float Bs[16][128];   // [k][n]

    const int tid = threadIdx.x;
    const int tc  = tid & 15;       // col group (8 cols: tc*4.. and 64+tc*4..)
    const int tr  = tid >> 4;       // row group (4 rows tr*4..)
    const int bm0 = blockIdx.x * 64;

    unsigned long long acc[4][4];
#pragma unroll
    for (int i = 0; i < 4; i++)
#pragma unroll
        for (int j = 0; j < 4; j++) acc[i][j] = 0ull;

    const int lr = tid >> 2;        // 0..63 : A tile row
    const int lq = tid & 3;         // 0..3  : which float4 of the 16-wide k slab
    int arow = bm0 + lr; if (arow >= M) arow = M - 1;   // clamp (in-bounds read)
    const float *Aptr = A + (size_t)arow * K + lq * 4;

    for (int k0 = 0; k0 < K; k0 += 16) {
        float4 av = *(const float4 *)(Aptr + k0);
        As[lq * 4 + 0][lr] = av.x;
        As[lq * 4 + 1][lr] = av.y;
        As[lq * 4 + 2][lr] = av.z;
        As[lq * 4 + 3][lr] = av.w;
#pragma unroll
        for (int it = 0; it < 2; ++it) {
            int f  = tid + it * 256;          // 0..511 float4s of the B tile
            int kk = f >> 5;
            int c4 = (f & 31) * 4;
            *(float4 *)&Bs[kk][c4] =
                *(const float4 *)&B[(size_t)(k0 + kk) * HID + c4];
        }
        __syncthreads();
#pragma unroll
        for (int k = 0; k < 16; ++k) {
            float4 a4 = *(const float4 *)&As[k][tr * 4];
            ulonglong2 b0 = *(const ulonglong2 *)&Bs[k][tc * 4];
            ulonglong2 b1 = *(const ulonglong2 *)&Bs[k][64 + tc * 4];
            unsigned long long aa;
            aa = pk2(a4.x);
            fma2(acc[0][0], aa, b0.x); fma2(acc[0][1], aa, b0.y);
            fma2(acc[0][2], aa, b1.x); fma2(acc[0][3], aa, b1.y);
            aa = pk2(a4.y);
            fma2(acc[1][0], aa, b0.x); fma2(acc[1][1], aa, b0.y);
            fma2(acc[1][2], aa, b1.x); fma2(acc[1][3], aa, b1.y);
            aa = pk2(a4.z);
            fma2(acc[2][0], aa, b0.x); fma2(acc[2][1], aa, b0.y);
            fma2(acc[2][2], aa, b1.x); fma2(acc[2][3], aa, b1.y);
            aa = pk2(a4.w);
            fma2(acc[3][0], aa, b0.x); fma2(acc[3][1], aa, b0.y);
            fma2(acc[3][2], aa, b1.x); fma2(acc[3][3], aa, b1.y);
        }
        __syncthreads();
    }

    const int c0 = tc * 4, c1 = 64 + tc * 4;
    float4 bb0 = bias ? *(const float4 *)&bias[c0] : make_float4(0.f, 0.f, 0.f, 0.f);
    float4 bb1 = bias ? *(const float4 *)&bias[c1] : make_float4(0.f, 0.f, 0.f, 0.f);
#pragma unroll
    for (int i = 0; i < 4; i++) {
        int row = bm0 + tr * 4 + i;
        if (row < M) {
            float s = dinv ? dinv[row] : 1.0f;
            float4 o0, o1;
            upk(acc[i][0], o0.x, o0.y); upk(acc[i][1], o0.z, o0.w);
            upk(acc[i][2], o1.x, o1.y); upk(acc[i][3], o1.z, o1.w);
            o0.x = fmaf(o0.x, s, bb0.x); o0.y = fmaf(o0.y, s, bb0.y);
            o0.z = fmaf(o0.z, s, bb0.z); o0.w = fmaf(o0.w, s, bb0.w);
            o1.x = fmaf(o1.x, s, bb1.x); o1.y = fmaf(o1.y, s, bb1.y);
            o1.z = fmaf(o1.z, s, bb1.z); o1.w = fmaf(o1.w, s, bb1.w);
            *(float4 *)&C[(size_t)row * HID + c0] = o0;
            *(float4 *)&C[(size_t)row * HID + c1] = o1;
        }
    }
}

// ---------------- edge scatter: agg[dst] += hs[src]  (warp per edge) ------
__global__ void k_scatter(const int *__restrict__ ei, int E,
                          const float *__restrict__ hs, float *__restrict__ agg)
{
    int w = (blockIdx.x * blockDim.x + threadIdx.x) >> 5;
    if (w >= E) return;
    int lane = threadIdx.x & 31;
    int s = ei[w];
    int d = ei[E + w];
    float4 v = *(const float4 *)&hs[(size_t)s * HID + lane * 4];
    red4(&agg[(size_t)d * HID + lane * 4], v);
}

// ---------------- finalize: out = dinv*(agg+hs)+bias (opt relu) -----------
__global__ void k_finalize(const float *__restrict__ agg, const float *__restrict__ hs,
                           const float *__restrict__ dinv, const float *__restrict__ bias,
                           float *__restrict__ out, int relu, int N)
{
    int t = blockIdx.x * blockDim.x + threadIdx.x;
    if (t >= N * 32) return;
    int v = t >> 5;
    int c = (t & 31) * 4;
    float dv = dinv[v];
    float4 a = *(const float4 *)&agg[(size_t)v * HID + c];
    float4 h = *(const float4 *)&hs[(size_t)v * HID + c];
    float4 b = *(const float4 *)&bias[c];
    float4 o;
    o.x = fmaf(dv, a.x + h.x, b.x);
    o.y = fmaf(dv, a.y + h.y, b.y);
    o.z = fmaf(dv, a.z + h.z, b.z);
    o.w = fmaf(dv, a.w + h.w, b.w);
    if (relu) {
        o.x = fmaxf(o.x, 0.f); o.y = fmaxf(o.y, 0.f);
        o.z = fmaxf(o.z, 0.f); o.w = fmaxf(o.w, 0.f);
    }
    *(float4 *)&out[(size_t)v * HID + c] = o;
}

// ---------------- pooling: warp per node ----------------------------------
__global__ void k_pool(const int *__restrict__ batch, int N,
                       const float *__restrict__ h, float *__restrict__ pool)
{
    int w = (blockIdx.x * blockDim.x + threadIdx.x) >> 5;
    if (w >= N) return;
    int lane = threadIdx.x & 31;
    int b = batch[w];
    float4 v = *(const float4 *)&h[(size_t)w * HID + lane * 4];
    red4(&pool[(size_t)b * HID + lane * 4], v);
    if (lane == 0) atomicAdd(&pool[NGRAPH * HID + b], 1.0f);
}

// ---------------- head MLP: block per graph -------------------------------
__global__ void k_head(const float *__restrict__ pool,
                       const float *__restrict__ W1, const float *__restrict__ b1,
                       const float *__restrict__ W2, const float *__restrict__ b2,
                       float *__restrict__ out)
{
    __shared__ float gv[HID];
    __shared__ float hid[HID];
    int g = blockIdx.x, t = threadIdx.x;
    float cnt = fmaxf(pool[NGRAPH * HID + g], 1.0f);
    gv[t] = pool[(size_t)g * HID + t] / cnt;
    __syncthreads();
    float acc = b1[t];
#pragma unroll 8
    for (int c = 0; c < HID; ++c) acc = fmaf(gv[c], W1[c * HID + t], acc);
    hid[t] = fmaxf(acc, 0.f);
    __syncthreads();
    if (t < NCLS) {
        float o = b2[t];
#pragma unroll 8
        for (int hh = 0; hh < HID; ++hh) o = fmaf(hid[hh], W2[hh * NCLS + t], o);
        out[g * NCLS + t] = o;
    }
}

// ---------------- launcher -------------------------------------------------
extern "C" void kernel_launch(void *const *d_in, const int *in_sizes, int n_in,
                              void *d_out, int out_size)
{
    const float *x     = (const float *)d_in[0];
    const int   *ei    = (const int *)d_in[1];
    const int   *batch = (const int *)d_in[2];
    const float *W_emb = (const float *)d_in[3], *b_emb = (const float *)d_in[4];
    const float *W_c1  = (const float *)d_in[5], *b_c1  = (const float *)d_in[6];
    const float *W_c2  = (const float *)d_in[7], *b_c2  = (const float *)d_in[8];
    const float *W_l1  = (const float *)d_in[9], *b_l1  = (const float *)d_in[10];
    const float *W_l2  = (const float *)d_in[11], *b_l2 = (const float *)d_in[12];
    float *out = (float *)d_out;

    const int E = in_sizes[1] / 2;
    const int N = in_sizes[2];
    const int K_IN = in_sizes[0] / N;

    static float *p_h = nullptr, *p_hs = nullptr, *p_agg = nullptr,
                 *p_dinv = nullptr, *p_pool = nullptr;
    static int *p_deg = nullptr;
    if (!p_h) {
        cudaGetSymbolAddress((void **)&p_h,    g_h);
        cudaGetSymbolAddress((void **)&p_hs,   g_hs);
        cudaGetSymbolAddress((void **)&p_agg,  g_agg);
        cudaGetSymbolAddress((void **)&p_dinv, g_dinv);
        cudaGetSymbolAddress((void **)&p_pool, g_pool);
        cudaGetSymbolAddress((void **)&p_deg,  g_deg);
    }

    const int gemm_grid = (N + 63) / 64;
    const int fin_grid  = (N * 32 + 255) / 256;
    const int edge_warp_grid = (E + 7) / 8;
    const int n4_agg = (N * HID) / 4;
    const int zero_grid = (n4_agg + 255) / 256;

    // degrees
    k_zero_deg<<<(N + 255) / 256, 256>>>(p_deg, N);
    k_deg <<<(E + 255) / 256, 256>>>(ei, E);
    k_dinv<<<(N + 255) / 256, 256>>>(N);

    // h0 = x @ W_emb + b_emb
    gemm128<<<gemm_grid, 256>>>(x, W_emb, b_emb, nullptr, p_h, N, K_IN);

    // conv1
    gemm128<<<gemm_grid, 256>>>(p_h, W_c1, nullptr, p_dinv, p_hs, N, HID);
    k_zero4<<<zero_grid, 256>>>((float4 *)p_agg, n4_agg);
    k_scatter <<<edge_warp_grid, 256>>>(ei, E, p_hs, p_agg);
    k_finalize<<<fin_grid, 256>>>(p_agg, p_hs, p_dinv, b_c1, p_h, 1, N);

    // conv2
    gemm128<<<gemm_grid, 256>>>(p_h, W_c2, nullptr, p_dinv, p_hs, N, HID);
    k_zero4<<<zero_grid, 256>>>((float4 *)p_agg, n4_agg);
    k_scatter <<<edge_warp_grid, 256>>>(ei, E, p_hs, p_agg);
    k_finalize<<<fin_grid, 256>>>(p_agg, p_hs, p_dinv, b_c2, p_h, 0, N);

    // pool + head
    k_zero4<<<(NGRAPH * (HID + 1) / 4 + 255) / 256, 256>>>((float4 *)p_pool,
                                                           NGRAPH * (HID + 1) / 4);
    k_pool<<<(N + 7) / 8, 256>>>(batch, N, p_h, p_pool);
    k_head<<<NGRAPH, HID>>>(p_pool, W_l1, b_l1, W_l2, b_l2, out);
}

// round 7
// speedup vs baseline: 1.2282x; 1.2282x over previous
#include <cuda_runtime.h>
#include <cuda_bf16.h>
#include <cstdint>

#define NNODES  50000
#define HID     128
#define INDIM   768
#define NGRAPH  128
#define NCLS    3

// ---------------- scratch (static device globals; no allocation) ----------
__device__ float g_h   [NNODES * HID];
__device__ float g_hs  [NNODES * HID];
__device__ float g_agg [NNODES * HID];
__device__ float g_dinv[NNODES];
__device__ int   g_deg [NNODES];
__device__ float g_pool[NGRAPH * HID + NGRAPH];
// bf16 split weights, transposed to [N=HID, K] K-major
__device__ __nv_bfloat16 g_Wemb_h[HID * INDIM], g_Wemb_l[HID * INDIM];
__device__ __nv_bfloat16 g_Wc1_h [HID * HID],   g_Wc1_l [HID * HID];
__device__ __nv_bfloat16 g_Wc2_h [HID * HID],   g_Wc2_l [HID * HID];

// ---------------- helpers ---------------------------------------------------
__device__ __forceinline__ uint32_t s2u(const void *p) {
    uint32_t a;
    asm("{ .reg .u64 t; cvta.to.shared.u64 t, %1; cvt.u32.u64 %0, t; }"
        : "=r"(a) : "l"(p));
    return a;
}
__device__ __forceinline__ void red4(float *p, float4 v) {
    asm volatile("red.global.add.v4.f32 [%0], {%1, %2, %3, %4};"
                 :: "l"(p), "f"(v.x), "f"(v.y), "f"(v.z), "f"(v.w) : "memory");
}
__device__ __forceinline__ void ldsm4(uint32_t &r0, uint32_t &r1, uint32_t &r2,
                                      uint32_t &r3, uint32_t addr) {
    asm volatile("ldmatrix.sync.aligned.m8n8.x4.shared.b16 {%0,%1,%2,%3}, [%4];"
                 : "=r"(r0), "=r"(r1), "=r"(r2), "=r"(r3) : "r"(addr));
}
__device__ __forceinline__ void mma16816(float *c, const uint32_t *a,
                                         const uint32_t *b) {
    asm volatile(
        "mma.sync.aligned.m16n8k16.row.col.f32.bf16.bf16.f32 "
        "{%0,%1,%2,%3}, {%4,%5,%6,%7}, {%8,%9}, {%0,%1,%2,%3};"
        : "+f"(c[0]), "+f"(c[1]), "+f"(c[2]), "+f"(c[3])
        : "r"(a[0]), "r"(a[1]), "r"(a[2]), "r"(a[3]), "r"(b[0]), "r"(b[1]));
}

// ---------------- zero fill -------------------------------------------------
__global__ void k_zero4(float4 *__restrict__ p, int n4) {
    int i = blockIdx.x * blockDim.x + threadIdx.x;
    if (i < n4) p[i] = make_float4(0.f, 0.f, 0.f, 0.f);
}
__global__ void k_zero_deg(int *__restrict__ p, int n) {
    int i = blockIdx.x * blockDim.x + threadIdx.x;
    if (i < n) p[i] = 0;
}

// ---------------- degree / dinv --------------------------------------------
__global__ void k_deg(const int *__restrict__ ei, int E) {
    int i = blockIdx.x * blockDim.x + threadIdx.x;
    if (i < E) atomicAdd(&g_deg[ei[E + i]], 1);
}
__global__ void k_dinv(int N) {
    int i = blockIdx.x * blockDim.x + threadIdx.x;
    if (i < N) g_dinv[i] = rsqrtf((float)g_deg[i] + 1.0f);
}

// ---------------- W prep: split fp32 -> bf16 hi/lo, transpose to [N,K] ----
__global__ void k_prepW(const float *__restrict__ W, __nv_bfloat16 *__restrict__ Bh,
                        __nv_bfloat16 *__restrict__ Bl, int K) {
    int i = blockIdx.x * blockDim.x + threadIdx.x;
    if (i >= K * HID) return;
    int k = i / HID, n = i % HID;          // W is [K][HID] row-major
    float v = W[i];
    __nv_bfloat16 h = __float2bfloat16(v);
    __nv_bfloat16 l = __float2bfloat16(v - __bfloat162float(h));
    Bh[(size_t)n * K + k] = h;
    Bl[(size_t)n * K + k] = l;
}

// ---------------- HMMA GEMM: C[M,128] = A[M,K] @ Bt[128,K]^T ---------------
// mma.sync m16n8k16 bf16, 3-term split, fp32 acc.
// BM=64, BN=128, BK=64; 256 thr; 8 warps = 2m x 4n; warp tile m32 n32.
// SMEM: Ahi[0,8K) Alo[8K,16K) Bhi[16K,32K) Blo[32K,48K)
__global__ void __launch_bounds__(256, 2)
hmma_gemm(const float *__restrict__ A,
          const __nv_bfloat16 *__restrict__ Bhg,
          const __nv_bfloat16 *__restrict__ Blg,
          const float *__restrict__ bias, const float *__restrict__ dinv,
          float *__restrict__ C, int M, int K)
{
    extern __shared__ __align__(1024) char smem[];
    const uint32_t sb = s2u(smem);
    const int tid = threadIdx.x;
    const int wid = tid >> 5, lane = tid & 31;
    const int warp_m = wid & 1, warp_n = wid >> 1;
    const int bm0 = blockIdx.x * 64;

    // ---- loader indices ----
    const int alr = tid >> 2, alq = tid & 3;       // A: row 0..63, k-quarter
    int arow = bm0 + alr; if (arow >= M) arow = M - 1;
    const float *Ar = A + (size_t)arow * K + alq * 16;
    const uint32_t a_sw0 = (uint32_t)(alr * 128) + (((uint32_t)(alq * 32) ^ ((alr & 7) << 4)));
    const uint32_t a_sw1 = (uint32_t)(alr * 128) + (((uint32_t)(alq * 32 + 16) ^ ((alr & 7) << 4)));

    const int blr = tid >> 1, blq = tid & 1;       // B: n 0..127, k-half
    const __nv_bfloat16 *Bhr = Bhg + (size_t)blr * K + blq * 32;
    const __nv_bfloat16 *Blr = Blg + (size_t)blr * K + blq * 32;
    uint32_t b_sw[4];
#pragma unroll
    for (int j = 0; j < 4; ++j)
        b_sw[j] = (uint32_t)(blr * 128) +
                  (((uint32_t)(blq * 64 + j * 16)) ^ ((blr & 7) << 4));

    // ---- ldmatrix lane addresses (region-relative, per ks add/xor) ----
    const int sub = lane >> 3, lr8 = lane & 7;
    // A: mi tiles at warp_m*32 + mi*16
    uint32_t a_row[2], a_xr[2], a_kb[2];
#pragma unroll
    for (int mi = 0; mi < 2; ++mi) {
        int row = warp_m * 32 + mi * 16 + ((sub & 1) << 3) + lr8;
        a_row[mi] = (uint32_t)(row * 128);
        a_xr[mi]  = (uint32_t)((row & 7) << 4);
        a_kb[mi]  = (uint32_t)((sub >> 1) << 4);
    }
    // B: np tiles at warp_n*32 + np*16
    uint32_t b_row[2], b_xr[2], b_kb[2];
#pragma unroll
    for (int np = 0; np < 2; ++np) {
        int nr = warp_n * 32 + np * 16 + ((sub >> 1) << 3) + lr8;
        b_row[np] = (uint32_t)(nr * 128);
        b_xr[np]  = (uint32_t)((nr & 7) << 4);
        b_kb[np]  = (uint32_t)((sub & 1) << 4);
    }

    float acc[2][4][4];
#pragma unroll
    for (int mi = 0; mi < 2; ++mi)
#pragma unroll
        for (int ni = 0; ni < 4; ++ni)
#pragma unroll
            for (int q = 0; q < 4; ++q) acc[mi][ni][q] = 0.f;

    const int NC = K >> 6;
    for (int c = 0; c < NC; ++c) {
        const int k0 = c << 6;
        // ---- A fp32 -> bf16 hi/lo ----
        {
            float4 v0 = *(const float4 *)(Ar + k0);
            float4 v1 = *(const float4 *)(Ar + k0 + 4);
            float4 v2 = *(const float4 *)(Ar + k0 + 8);
            float4 v3 = *(const float4 *)(Ar + k0 + 12);
            __nv_bfloat162 h0 = __floats2bfloat162_rn(v0.x, v0.y);
            __nv_bfloat162 h1 = __floats2bfloat162_rn(v0.z, v0.w);
            __nv_bfloat162 h2 = __floats2bfloat162_rn(v1.x, v1.y);
            __nv_bfloat162 h3 = __floats2bfloat162_rn(v1.z, v1.w);
            __nv_bfloat162 h4 = __floats2bfloat162_rn(v2.x, v2.y);
            __nv_bfloat162 h5 = __floats2bfloat162_rn(v2.z, v2.w);
            __nv_bfloat162 h6 = __floats2bfloat162_rn(v3.x, v3.y);
            __nv_bfloat162 h7 = __floats2bfloat162_rn(v3.z, v3.w);
            __nv_bfloat162 l0 = __floats2bfloat162_rn(v0.x - __bfloat162float(h0.x), v0.y - __bfloat162float(h0.y));
            __nv_bfloat162 l1 = __floats2bfloat162_rn(v0.z - __bfloat162float(h1.x), v0.w - __bfloat162float(h1.y));
            __nv_bfloat162 l2 = __floats2bfloat162_rn(v1.x - __bfloat162float(h2.x), v1.y - __bfloat162float(h2.y));
            __nv_bfloat162 l3 = __floats2bfloat162_rn(v1.z - __bfloat162float(h3.x), v1.w - __bfloat162float(h3.y));
            __nv_bfloat162 l4 = __floats2bfloat162_rn(v2.x - __bfloat162float(h4.x), v2.y - __bfloat162float(h4.y));
            __nv_bfloat162 l5 = __floats2bfloat162_rn(v2.z - __bfloat162float(h5.x), v2.w - __bfloat162float(h5.y));
            __nv_bfloat162 l6 = __floats2bfloat162_rn(v3.x - __bfloat162float(h6.x), v3.y - __bfloat162float(h6.y));
            __nv_bfloat162 l7 = __floats2bfloat162_rn(v3.z - __bfloat162float(h7.x), v3.w - __bfloat162float(h7.y));
            *(uint4 *)(smem + a_sw0) = make_uint4(*(uint32_t *)&h0, *(uint32_t *)&h1, *(uint32_t *)&h2, *(uint32_t *)&h3);
            *(uint4 *)(smem + a_sw1) = make_uint4(*(uint32_t *)&h4, *(uint32_t *)&h5, *(uint32_t *)&h6, *(uint32_t *)&h7);
            *(uint4 *)(smem + 8192 + a_sw0) = make_uint4(*(uint32_t *)&l0, *(uint32_t *)&l1, *(uint32_t *)&l2, *(uint32_t *)&l3);
            *(uint4 *)(smem + 8192 + a_sw1) = make_uint4(*(uint32_t *)&l4, *(uint32_t *)&l5, *(uint32_t *)&l6, *(uint32_t *)&l7);
        }
        // ---- B bf16 hi/lo copy ----
#pragma unroll
        for (int j = 0; j < 4; ++j) {
            *(uint4 *)(smem + 16384 + b_sw[j]) = *(const uint4 *)(Bhr + k0 + j * 8);
            *(uint4 *)(smem + 32768 + b_sw[j]) = *(const uint4 *)(Blr + k0 + j * 8);
        }
        __syncthreads();

#pragma unroll
        for (int ks = 0; ks < 4; ++ks) {
            uint32_t ahi[2][4], alo[2][4], bhi[4][2], blo[4][2];
#pragma unroll
            for (int mi = 0; mi < 2; ++mi) {
                uint32_t kb = (uint32_t)(ks * 32) + a_kb[mi];
                uint32_t ad = sb + a_row[mi] + (kb ^ a_xr[mi]);
                ldsm4(ahi[mi][0], ahi[mi][1], ahi[mi][2], ahi[mi][3], ad);
                ldsm4(alo[mi][0], alo[mi][1], alo[mi][2], alo[mi][3], ad + 8192);
            }
#pragma unroll
            for (int np = 0; np < 2; ++np) {
                uint32_t kb = (uint32_t)(ks * 32) + b_kb[np];
                uint32_t bd = sb + 16384 + b_row[np] + (kb ^ b_xr[np]);
                ldsm4(bhi[np * 2][0], bhi[np * 2][1], bhi[np * 2 + 1][0], bhi[np * 2 + 1][1], bd);
                ldsm4(blo[np * 2][0], blo[np * 2][1], blo[np * 2 + 1][0], blo[np * 2 + 1][1], bd + 16384);
            }
#pragma unroll
            for (int mi = 0; mi < 2; ++mi)
#pragma unroll
                for (int ni = 0; ni < 4; ++ni) {
                    mma16816(acc[mi][ni], ahi[mi], bhi[ni]);
                    mma16816(acc[mi][ni], ahi[mi], blo[ni]);
                    mma16816(acc[mi][ni], alo[mi], bhi[ni]);
                }
        }
        __syncthreads();
    }

    // ---- epilogue ----
    const int gid = lane >> 2, qid = lane & 3;
#pragma unroll
    for (int mi = 0; mi < 2; ++mi) {
        int row0 = bm0 + warp_m * 32 + mi * 16 + gid;
        int row1 = row0 + 8;
        float s0 = 1.f, s1 = 1.f;
        if (dinv) {
            if (row0 < M) s0 = dinv[row0];
            if (row1 < M) s1 = dinv[row1];
        }
#pragma unroll
        for (int ni = 0; ni < 4; ++ni) {
            int col = warp_n * 32 + ni * 8 + qid * 2;
            float b0 = 0.f, b1 = 0.f;
            if (bias) { b0 = bias[col]; b1 = bias[col + 1]; }
            if (row0 < M) {
                float2 o = make_float2(fmaf(acc[mi][ni][0], s0, b0),
                                       fmaf(acc[mi][ni][1], s0, b1));
                *(float2 *)&C[(size_t)row0 * HID + col] = o;
            }
            if (row1 < M) {
                float2 o = make_float2(fmaf(acc[mi][ni][2], s1, b0),
                                       fmaf(acc[mi][ni][3], s1, b1));
                *(float2 *)&C[(size_t)row1 * HID + col] = o;
            }
        }
    }
}

// ---------------- edge scatter: agg[dst] += hs[src]  (warp per edge) ------
__global__ void k_scatter(const int *__restrict__ ei, int E,
                          const float *__restrict__ hs, float *__restrict__ agg)
{
    int w = (blockIdx.x * blockDim.x + threadIdx.x) >> 5;
    if (w >= E) return;
    int lane = threadIdx.x & 31;
    int s = ei[w];
    int d = ei[E + w];
    float4 v = *(const float4 *)&hs[(size_t)s * HID + lane * 4];
    red4(&agg[(size_t)d * HID + lane * 4], v);
}

// ---------------- finalize: out = dinv*(agg+hs)+bias (opt relu) -----------
__global__ void k_finalize(const float *__restrict__ agg, const float *__restrict__ hs,
                           const float *__restrict__ dinv, const float *__restrict__ bias,
                           float *__restrict__ out, int relu, int N)
{
    int t = blockIdx.x * blockDim.x + threadIdx.x;
    if (t >= N * 32) return;
    int v = t >> 5;
    int c = (t & 31) * 4;
    float dv = dinv[v];
    float4 a = *(const float4 *)&agg[(size_t)v * HID + c];
    float4 h = *(const float4 *)&hs[(size_t)v * HID + c];
    float4 b = *(const float4 *)&bias[c];
    float4 o;
    o.x = fmaf(dv, a.x + h.x, b.x);
    o.y = fmaf(dv, a.y + h.y, b.y);
    o.z = fmaf(dv, a.z + h.z, b.z);
    o.w = fmaf(dv, a.w + h.w, b.w);
    if (relu) {
        o.x = fmaxf(o.x, 0.f); o.y = fmaxf(o.y, 0.f);
        o.z = fmaxf(o.z, 0.f); o.w = fmaxf(o.w, 0.f);
    }
    *(float4 *)&out[(size_t)v * HID + c] = o;
}

// ---------------- pooling: warp per node ----------------------------------
__global__ void k_pool(const int *__restrict__ batch, int N,
                       const float *__restrict__ h, float *__restrict__ pool)
{
    int w = (blockIdx.x * blockDim.x + threadIdx.x) >> 5;
    if (w >= N) return;
    int lane = threadIdx.x & 31;
    int b = batch[w];
    float4 v = *(const float4 *)&h[(size_t)w * HID + lane * 4];
    red4(&pool[(size_t)b * HID + lane * 4], v);
    if (lane == 0) atomicAdd(&pool[NGRAPH * HID + b], 1.0f);
}

// ---------------- head MLP: block per graph -------------------------------
__global__ void k_head(const float *__restrict__ pool,
                       const float *__restrict__ W1, const float *__restrict__ b1,
                       const float *__restrict__ W2, const float *__restrict__ b2,
                       float *__restrict__ out)
{
    __shared__ float gv[HID];
    __shared__ float hid[HID];
    int g = blockIdx.x, t = threadIdx.x;
    float cnt = fmaxf(pool[NGRAPH * HID + g], 1.0f);
    gv[t] = pool[(size_t)g * HID + t] / cnt;
    __syncthreads();
    float acc = b1[t];
#pragma unroll 8
    for (int c = 0; c < HID; ++c) acc = fmaf(gv[c], W1[c * HID + t], acc);
    hid[t] = fmaxf(acc, 0.f);
    __syncthreads();
    if (t < NCLS) {
        float o = b2[t];
#pragma unroll 8
        for (int hh = 0; hh < HID; ++hh) o = fmaf(hid[hh], W2[hh * NCLS + t], o);
        out[g * NCLS + t] = o;
    }
}

// ---------------- launcher -------------------------------------------------
#define MMA_SMEM 49152

extern "C" void kernel_launch(void *const *d_in, const int *in_sizes, int n_in,
                              void *d_out, int out_size)
{
    const float *x     = (const float *)d_in[0];
    const int   *ei    = (const int *)d_in[1];
    const int   *batch = (const int *)d_in[2];
    const float *W_emb = (const float *)d_in[3], *b_emb = (const float *)d_in[4];
    const float *W_c1  = (const float *)d_in[5], *b_c1  = (const float *)d_in[6];
    const float *W_c2  = (const float *)d_in[7], *b_c2  = (const float *)d_in[8];
    const float *W_l1  = (const float *)d_in[9], *b_l1  = (const float *)d_in[10];
    const float *W_l2  = (const float *)d_in[11], *b_l2 = (const float *)d_in[12];
    float *out = (float *)d_out;

    const int E = in_sizes[1] / 2;
    const int N = in_sizes[2];
    const int K_IN = in_sizes[0] / N;

    static float *p_h = nullptr, *p_hs = nullptr, *p_agg = nullptr,
                 *p_dinv = nullptr, *p_pool = nullptr;
    static int *p_deg = nullptr;
    static __nv_bfloat16 *p_We_h, *p_We_l, *p_W1_h, *p_W1_l, *p_W2_h, *p_W2_l;
    if (!p_h) {
        cudaGetSymbolAddress((void **)&p_h,    g_h);
        cudaGetSymbolAddress((void **)&p_hs,   g_hs);
        cudaGetSymbolAddress((void **)&p_agg,  g_agg);
        cudaGetSymbolAddress((void **)&p_dinv, g_dinv);
        cudaGetSymbolAddress((void **)&p_pool, g_pool);
        cudaGetSymbolAddress((void **)&p_deg,  g_deg);
        cudaGetSymbolAddress((void **)&p_We_h, g_Wemb_h);
        cudaGetSymbolAddress((void **)&p_We_l, g_Wemb_l);
        cudaGetSymbolAddress((void **)&p_W1_h, g_Wc1_h);
        cudaGetSymbolAddress((void **)&p_W1_l, g_Wc1_l);
        cudaGetSymbolAddress((void **)&p_W2_h, g_Wc2_h);
        cudaGetSymbolAddress((void **)&p_W2_l, g_Wc2_l);
        cudaFuncSetAttribute(hmma_gemm,
                             cudaFuncAttributeMaxDynamicSharedMemorySize, MMA_SMEM);
    }

    const int mma_grid = (N + 63) / 64;
    const int fin_grid  = (N * 32 + 255) / 256;
    const int edge_warp_grid = (E + 7) / 8;
    const int n4_agg = (N * HID) / 4;
    const int zero_grid = (n4_agg + 255) / 256;

    // weight prep (bf16 split + transpose)
    k_prepW<<<(K_IN * HID + 255) / 256, 256>>>(W_emb, p_We_h, p_We_l, K_IN);
    k_prepW<<<(HID * HID + 255) / 256, 256>>>(W_c1, p_W1_h, p_W1_l, HID);
    k_prepW<<<(HID * HID + 255) / 256, 256>>>(W_c2, p_W2_h, p_W2_l, HID);

    // degrees
    k_zero_deg<<<(N + 255) / 256, 256>>>(p_deg, N);
    k_deg <<<(E + 255) / 256, 256>>>(ei, E);
    k_dinv<<<(N + 255) / 256, 256>>>(N);

    // h0 = x @ W_emb + b_emb
    hmma_gemm<<<mma_grid, 256, MMA_SMEM>>>(x, p_We_h, p_We_l, b_emb, nullptr,
                                           p_h, N, K_IN);

    // conv1
    hmma_gemm<<<mma_grid, 256, MMA_SMEM>>>(p_h, p_W1_h, p_W1_l, nullptr, p_dinv,
                                           p_hs, N, HID);
    k_zero4<<<zero_grid, 256>>>((float4 *)p_agg, n4_agg);
    k_scatter <<<edge_warp_grid, 256>>>(ei, E, p_hs, p_agg);
    k_finalize<<<fin_grid, 256>>>(p_agg, p_hs, p_dinv, b_c1, p_h, 1, N);

    // conv2
    hmma_gemm<<<mma_grid, 256, MMA_SMEM>>>(p_h, p_W2_h, p_W2_l, nullptr, p_dinv,
                                           p_hs, N, HID);
    k_zero4<<<zero_grid, 256>>>((float4 *)p_agg, n4_agg);
    k_scatter <<<edge_warp_grid, 256>>>(ei, E, p_hs, p_agg);
    k_finalize<<<fin_grid, 256>>>(p_agg, p_hs, p_dinv, b_c2, p_h, 0, N);

    // pool + head
    k_zero4<<<(NGRAPH * (HID + 1) / 4 + 255) / 256, 256>>>((float4 *)p_pool,
                                                           NGRAPH * (HID + 1) / 4);
    k_pool<<<(N + 7) / 8, 256>>>(batch, N, p_h, p_pool);
    k_head<<<NGRAPH, HID>>>(p_pool, W_l1, b_l1, W_l2, b_l2, out);
}

// round 8
// speedup vs baseline: 1.3657x; 1.1119x over previous
#include <cuda_runtime.h>
#include <cuda_bf16.h>
#include <cstdint>

#define NNODES  50000
#define HID     128
#define INDIM   768
#define NGRAPH  128
#define NCLS    3

// GEMM tiling
#define BK      32
#define ASTRIDE 80              // 64B data + 16B pad
#define ABUF    5120            // 64 * 80
#define BBUF    10240           // 128 * 80
#define BUFSZ   30720           // 2*ABUF + 2*BBUF
#define MMA_SMEM (2 * BUFSZ)    // 61440

// ---------------- scratch (static device globals; no allocation) ----------
__device__ float g_h   [NNODES * HID];
__device__ float g_hs  [NNODES * HID];
__device__ float g_agg [NNODES * HID];
__device__ float g_dinv[NNODES];
__device__ int   g_deg [NNODES];
__device__ float g_pool[NGRAPH * HID + NGRAPH];
__device__ __nv_bfloat16 g_Wemb_h[HID * INDIM], g_Wemb_l[HID * INDIM];
__device__ __nv_bfloat16 g_Wc1_h [HID * HID],   g_Wc1_l [HID * HID];
__device__ __nv_bfloat16 g_Wc2_h [HID * HID],   g_Wc2_l [HID * HID];

// ---------------- helpers ---------------------------------------------------
__device__ __forceinline__ uint32_t s2u(const void *p) {
    uint32_t a;
    asm("{ .reg .u64 t; cvta.to.shared.u64 t, %1; cvt.u32.u64 %0, t; }"
        : "=r"(a) : "l"(p));
    return a;
}
__device__ __forceinline__ void red4(float *p, float4 v) {
    asm volatile("red.global.add.v4.f32 [%0], {%1, %2, %3, %4};"
                 :: "l"(p), "f"(v.x), "f"(v.y), "f"(v.z), "f"(v.w) : "memory");
}
__device__ __forceinline__ void ldsm4(uint32_t &r0, uint32_t &r1, uint32_t &r2,
                                      uint32_t &r3, uint32_t addr) {
    asm volatile("ldmatrix.sync.aligned.m8n8.x4.shared.b16 {%0,%1,%2,%3}, [%4];"
                 : "=r"(r0), "=r"(r1), "=r"(r2), "=r"(r3) : "r"(addr));
}
__device__ __forceinline__ void mma16816(float *c, const uint32_t *a,
                                         const uint32_t *b) {
    asm volatile(
        "mma.sync.aligned.m16n8k16.row.col.f32.bf16.bf16.f32 "
        "{%0,%1,%2,%3}, {%4,%5,%6,%7}, {%8,%9}, {%0,%1,%2,%3};"
        : "+f"(c[0]), "+f"(c[1]), "+f"(c[2]), "+f"(c[3])
        : "r"(a[0]), "r"(a[1]), "r"(a[2]), "r"(a[3]), "r"(b[0]), "r"(b[1]));
}
__device__ __forceinline__ void cpa16(uint32_t s, const void *g) {
    asm volatile("cp.async.cg.shared.global [%0], [%1], 16;" :: "r"(s), "l"(g));
}

// ---------------- zero fill -------------------------------------------------
__global__ void k_zero4(float4 *__restrict__ p, int n4) {
    int i = blockIdx.x * blockDim.x + threadIdx.x;
    if (i < n4) p[i] = make_float4(0.f, 0.f, 0.f, 0.f);
}
__global__ void k_zero_deg(int *__restrict__ p, int n) {
    int i = blockIdx.x * blockDim.x + threadIdx.x;
    if (i < n) p[i] = 0;
}

// ---------------- degree / dinv --------------------------------------------
__global__ void k_deg(const int *__restrict__ ei, int E) {
    int i = blockIdx.x * blockDim.x + threadIdx.x;
    if (i < E) atomicAdd(&g_deg[ei[E + i]], 1);
}
__global__ void k_dinv(int N) {
    int i = blockIdx.x * blockDim.x + threadIdx.x;
    if (i < N) g_dinv[i] = rsqrtf((float)g_deg[i] + 1.0f);
}

// ---------------- W prep: split fp32 -> bf16 hi/lo, transpose to [N,K] ----
__global__ void k_prepW(const float *__restrict__ W, __nv_bfloat16 *__restrict__ Bh,
                        __nv_bfloat16 *__restrict__ Bl, int K) {
    int i = blockIdx.x * blockDim.x + threadIdx.x;
    if (i >= K * HID) return;
    int k = i / HID, n = i % HID;
    float v = W[i];
    __nv_bfloat16 h = __float2bfloat16(v);
    __nv_bfloat16 l = __float2bfloat16(v - __bfloat162float(h));
    Bh[(size_t)n * K + k] = h;
    Bl[(size_t)n * K + k] = l;
}

// ---------------- HMMA GEMM (double-buffered, cp.async) --------------------
// C[M,128] = A[M,K] @ Bt[128,K]^T, bf16 3-term split, fp32 acc.
// BM=64, BN=128, BK=32; 256 thr; warps 2m x 4n; warp tile m32 n32.
// per-buffer: Ahi[0,5120) Alo[5120,10240) Bhi[10240,20480) Blo[20480,30720)
__global__ void __launch_bounds__(256, 2)
hmma_gemm(const float *__restrict__ A,
          const __nv_bfloat16 *__restrict__ Bhg,
          const __nv_bfloat16 *__restrict__ Blg,
          const float *__restrict__ bias, const float *__restrict__ dinv,
          float *__restrict__ C, int M, int K)
{
    extern __shared__ __align__(1024) char smem[];
    const uint32_t sb = s2u(smem);
    const int tid = threadIdx.x;
    const int wid = tid >> 5, lane = tid & 31;
    const int warp_m = wid & 1, warp_n = wid >> 1;
    const int bm0 = blockIdx.x * 64;

    // A loader: row = tid>>2 (0..63), q = tid&3 (8 k-elems each)
    const int alr = tid >> 2, alq = tid & 3;
    int arow = bm0 + alr; if (arow >= M) arow = M - 1;
    const float *Ar = A + (size_t)arow * K + alq * 8;
    const uint32_t a_sts = (uint32_t)(alr * ASTRIDE + alq * 16);

    // B loader: n = tid>>1 (0..127), u = tid&1 (16 k-elems each)
    const int bln = tid >> 1, blu = tid & 1;
    const __nv_bfloat16 *Bhr = Bhg + (size_t)bln * K + blu * 16;
    const __nv_bfloat16 *Blr = Blg + (size_t)bln * K + blu * 16;
    const uint32_t b_sts = (uint32_t)(bln * ASTRIDE + blu * 32);

    // fragment lane offsets
    const int sub = lane >> 3, lr8 = lane & 7;
    uint32_t a_off[2], b_off[2];
#pragma unroll
    for (int mi = 0; mi < 2; ++mi) {
        int row = warp_m * 32 + mi * 16 + ((sub & 1) << 3) + lr8;
        a_off[mi] = (uint32_t)(row * ASTRIDE + ((sub >> 1) << 4));
    }
#pragma unroll
    for (int np = 0; np < 2; ++np) {
        int nr = warp_n * 32 + np * 16 + ((sub >> 1) << 3) + lr8;
        b_off[np] = (uint32_t)(nr * ASTRIDE + ((sub & 1) << 4));
    }

    float acc[2][4][4];
#pragma unroll
    for (int mi = 0; mi < 2; ++mi)
#pragma unroll
        for (int ni = 0; ni < 4; ++ni)
#pragma unroll
            for (int q = 0; q < 4; ++q) acc[mi][ni][q] = 0.f;

    const int NC = K / BK;
    float4 va0, va1;

    // ---- prologue: stage chunk 0 into buffer 0 ----
    va0 = *(const float4 *)(Ar);
    va1 = *(const float4 *)(Ar + 4);
    {
        uint32_t s0 = sb + 2 * ABUF + b_sts;
        cpa16(s0,            Bhr);
        cpa16(s0 + 16,       Bhr + 8);
        cpa16(s0 + BBUF,     Blr);
        cpa16(s0 + BBUF + 16, Blr + 8);
        asm volatile("cp.async.commit_group;" ::: "memory");
    }
    {
        __nv_bfloat162 h0 = __floats2bfloat162_rn(va0.x, va0.y);
        __nv_bfloat162 h1 = __floats2bfloat162_rn(va0.z, va0.w);
        __nv_bfloat162 h2 = __floats2bfloat162_rn(va1.x, va1.y);
        __nv_bfloat162 h3 = __floats2bfloat162_rn(va1.z, va1.w);
        __nv_bfloat162 l0 = __floats2bfloat162_rn(va0.x - __bfloat162float(h0.x), va0.y - __bfloat162float(h0.y));
        __nv_bfloat162 l1 = __floats2bfloat162_rn(va0.z - __bfloat162float(h1.x), va0.w - __bfloat162float(h1.y));
        __nv_bfloat162 l2 = __floats2bfloat162_rn(va1.x - __bfloat162float(h2.x), va1.y - __bfloat162float(h2.y));
        __nv_bfloat162 l3 = __floats2bfloat162_rn(va1.z - __bfloat162float(h3.x), va1.w - __bfloat162float(h3.y));
        *(uint4 *)(smem + a_sts) =
            make_uint4(*(uint32_t *)&h0, *(uint32_t *)&h1, *(uint32_t *)&h2, *(uint32_t *)&h3);
        *(uint4 *)(smem + ABUF + a_sts) =
            make_uint4(*(uint32_t *)&l0, *(uint32_t *)&l1, *(uint32_t *)&l2, *(uint32_t *)&l3);
    }
    asm volatile("cp.async.wait_group 0;" ::: "memory");
    __syncthreads();

    for (int c = 0; c < NC; ++c) {
        const uint32_t bo = (c & 1) ? (uint32_t)BUFSZ : 0u;
        const uint32_t bn = (c & 1) ? 0u : (uint32_t)BUFSZ;
        const bool more = (c + 1 < NC);
        if (more) {
            const int k1 = (c + 1) * BK;
            va0 = *(const float4 *)(Ar + k1);
            va1 = *(const float4 *)(Ar + k1 + 4);
            uint32_t s0 = sb + bn + 2 * ABUF + b_sts;
            cpa16(s0,             Bhr + k1);
            cpa16(s0 + 16,        Bhr + k1 + 8);
            cpa16(s0 + BBUF,      Blr + k1);
            cpa16(s0 + BBUF + 16, Blr + k1 + 8);
            asm volatile("cp.async.commit_group;" ::: "memory");
        }

#pragma unroll
        for (int ks = 0; ks < 2; ++ks) {
            uint32_t ahi[2][4], alo[2][4], bhi[4][2], blo[4][2];
#pragma unroll
            for (int mi = 0; mi < 2; ++mi) {
                uint32_t ad = sb + bo + a_off[mi] + ks * 32;
                ldsm4(ahi[mi][0], ahi[mi][1], ahi[mi][2], ahi[mi][3], ad);
                ldsm4(alo[mi][0], alo[mi][1], alo[mi][2], alo[mi][3], ad + ABUF);
            }
#pragma unroll
            for (int np = 0; np < 2; ++np) {
                uint32_t bd = sb + bo + 2 * ABUF + b_off[np] + ks * 32;
                ldsm4(bhi[np * 2][0], bhi[np * 2][1],
                      bhi[np * 2 + 1][0], bhi[np * 2 + 1][1], bd);
                ldsm4(blo[np * 2][0], blo[np * 2][1],
                      blo[np * 2 + 1][0], blo[np * 2 + 1][1], bd + BBUF);
            }
#pragma unroll
            for (int mi = 0; mi < 2; ++mi)
#pragma unroll
                for (int ni = 0; ni < 4; ++ni) {
                    mma16816(acc[mi][ni], ahi[mi], bhi[ni]);
                    mma16816(acc[mi][ni], ahi[mi], blo[ni]);
                    mma16816(acc[mi][ni], alo[mi], bhi[ni]);
                }
        }

        if (more) {
            __nv_bfloat162 h0 = __floats2bfloat162_rn(va0.x, va0.y);
            __nv_bfloat162 h1 = __floats2bfloat162_rn(va0.z, va0.w);
            __nv_bfloat162 h2 = __floats2bfloat162_rn(va1.x, va1.y);
            __nv_bfloat162 h3 = __floats2bfloat162_rn(va1.z, va1.w);
            __nv_bfloat162 l0 = __floats2bfloat162_rn(va0.x - __bfloat162float(h0.x), va0.y - __bfloat162float(h0.y));
            __nv_bfloat162 l1 = __floats2bfloat162_rn(va0.z - __bfloat162float(h1.x), va0.w - __bfloat162float(h1.y));
            __nv_bfloat162 l2 = __floats2bfloat162_rn(va1.x - __bfloat162float(h2.x), va1.y - __bfloat162float(h2.y));
            __nv_bfloat162 l3 = __floats2bfloat162_rn(va1.z - __bfloat162float(h3.x), va1.w - __bfloat162float(h3.y));
            *(uint4 *)(smem + bn + a_sts) =
                make_uint4(*(uint32_t *)&h0, *(uint32_t *)&h1, *(uint32_t *)&h2, *(uint32_t *)&h3);
            *(uint4 *)(smem + bn + ABUF + a_sts) =
                make_uint4(*(uint32_t *)&l0, *(uint32_t *)&l1, *(uint32_t *)&l2, *(uint32_t *)&l3);
            asm volatile("cp.async.wait_group 0;" ::: "memory");
        }
        __syncthreads();
    }

    // ---- epilogue ----
    const int gid = lane >> 2, qid = lane & 3;
#pragma unroll
    for (int mi = 0; mi < 2; ++mi) {
        int row0 = bm0 + warp_m * 32 + mi * 16 + gid;
        int row1 = row0 + 8;
        float s0 = 1.f, s1 = 1.f;
        if (dinv) {
            if (row0 < M) s0 = dinv[row0];
            if (row1 < M) s1 = dinv[row1];
        }
#pragma unroll
        for (int ni = 0; ni < 4; ++ni) {
            int col = warp_n * 32 + ni * 8 + qid * 2;
            float b0 = 0.f, b1 = 0.f;
            if (bias) { b0 = bias[col]; b1 = bias[col + 1]; }
            if (row0 < M) {
                float2 o = make_float2(fmaf(acc[mi][ni][0], s0, b0),
                                       fmaf(acc[mi][ni][1], s0, b1));
                *(float2 *)&C[(size_t)row0 * HID + col] = o;
            }
            if (row1 < M) {
                float2 o = make_float2(fmaf(acc[mi][ni][2], s1, b0),
                                       fmaf(acc[mi][ni][3], s1, b1));
                *(float2 *)&C[(size_t)row1 * HID + col] = o;
            }
        }
    }
}

// ---------------- edge scatter: agg[dst] += hs[src]  (warp per edge) ------
__global__ void k_scatter(const int *__restrict__ ei, int E,
                          const float *__restrict__ hs, float *__restrict__ agg)
{
    int w = (blockIdx.x * blockDim.x + threadIdx.x) >> 5;
    if (w >= E) return;
    int lane = threadIdx.x & 31;
    int s = ei[w];
    int d = ei[E + w];
    float4 v = *(const float4 *)&hs[(size_t)s * HID + lane * 4];
    red4(&agg[(size_t)d * HID + lane * 4], v);
}

// ---------------- finalize: out = dinv*(agg+hs)+bias (opt relu) -----------
__global__ void k_finalize(const float *__restrict__ agg, const float *__restrict__ hs,
                           const float *__restrict__ dinv, const float *__restrict__ bias,
                           float *__restrict__ out, int relu, int N)
{
    int t = blockIdx.x * blockDim.x + threadIdx.x;
    if (t >= N * 32) return;
    int v = t >> 5;
    int c = (t & 31) * 4;
    float dv = dinv[v];
    float4 a = *(const float4 *)&agg[(size_t)v * HID + c];
    float4 h = *(const float4 *)&hs[(size_t)v * HID + c];
    float4 b = *(const float4 *)&bias[c];
    float4 o;
    o.x = fmaf(dv, a.x + h.x, b.x);
    o.y = fmaf(dv, a.y + h.y, b.y);
    o.z = fmaf(dv, a.z + h.z, b.z);
    o.w = fmaf(dv, a.w + h.w, b.w);
    if (relu) {
        o.x = fmaxf(o.x, 0.f); o.y = fmaxf(o.y, 0.f);
        o.z = fmaxf(o.z, 0.f); o.w = fmaxf(o.w, 0.f);
    }
    *(float4 *)&out[(size_t)v * HID + c] = o;
}

// ---------------- pooling: warp per node ----------------------------------
__global__ void k_pool(const int *__restrict__ batch, int N,
                       const float *__restrict__ h, float *__restrict__ pool)
{
    int w = (blockIdx.x * blockDim.x + threadIdx.x) >> 5;
    if (w >= N) return;
    int lane = threadIdx.x & 31;
    int b = batch[w];
    float4 v = *(const float4 *)&h[(size_t)w * HID + lane * 4];
    red4(&pool[(size_t)b * HID + lane * 4], v);
    if (lane == 0) atomicAdd(&pool[NGRAPH * HID + b], 1.0f);
}

// ---------------- head MLP: block per graph -------------------------------
__global__ void k_head(const float *__restrict__ pool,
                       const float *__restrict__ W1, const float *__restrict__ b1,
                       const float *__restrict__ W2, const float *__restrict__ b2,
                       float *__restrict__ out)
{
    __shared__ float gv[HID];
    __shared__ float hid[HID];
    int g = blockIdx.x, t = threadIdx.x;
    float cnt = fmaxf(pool[NGRAPH * HID + g], 1.0f);
    gv[t] = pool[(size_t)g * HID + t] / cnt;
    __syncthreads();
    float acc = b1[t];
#pragma unroll 8
    for (int c = 0; c < HID; ++c) acc = fmaf(gv[c], W1[c * HID + t], acc);
    hid[t] = fmaxf(acc, 0.f);
    __syncthreads();
    if (t < NCLS) {
        float o = b2[t];
#pragma unroll 8
        for (int hh = 0; hh < HID; ++hh) o = fmaf(hid[hh], W2[hh * NCLS + t], o);
        out[g * NCLS + t] = o;
    }
}

// ---------------- launcher -------------------------------------------------
extern "C" void kernel_launch(void *const *d_in, const int *in_sizes, int n_in,
                              void *d_out, int out_size)
{
    const float *x     = (const float *)d_in[0];
    const int   *ei    = (const int *)d_in[1];
    const int   *batch = (const int *)d_in[2];
    const float *W_emb = (const float *)d_in[3], *b_emb = (const float *)d_in[4];
    const float *W_c1  = (const float *)d_in[5], *b_c1  = (const float *)d_in[6];
    const float *W_c2  = (const float *)d_in[7], *b_c2  = (const float *)d_in[8];
    const float *W_l1  = (const float *)d_in[9], *b_l1  = (const float *)d_in[10];
    const float *W_l2  = (const float *)d_in[11], *b_l2 = (const float *)d_in[12];
    float *out = (float *)d_out;

    const int E = in_sizes[1] / 2;
    const int N = in_sizes[2];
    const int K_IN = in_sizes[0] / N;

    static float *p_h = nullptr, *p_hs = nullptr, *p_agg = nullptr,
                 *p_dinv = nullptr, *p_pool = nullptr;
    static int *p_deg = nullptr;
    static __nv_bfloat16 *p_We_h, *p_We_l, *p_W1_h, *p_W1_l, *p_W2_h, *p_W2_l;
    if (!p_h) {
        cudaGetSymbolAddress((void **)&p_h,    g_h);
        cudaGetSymbolAddress((void **)&p_hs,   g_hs);
        cudaGetSymbolAddress((void **)&p_agg,  g_agg);
        cudaGetSymbolAddress((void **)&p_dinv, g_dinv);
        cudaGetSymbolAddress((void **)&p_pool, g_pool);
        cudaGetSymbolAddress((void **)&p_deg,  g_deg);
        cudaGetSymbolAddress((void **)&p_We_h, g_Wemb_h);
        cudaGetSymbolAddress((void **)&p_We_l, g_Wemb_l);
        cudaGetSymbolAddress((void **)&p_W1_h, g_Wc1_h);
        cudaGetSymbolAddress((void **)&p_W1_l, g_Wc1_l);
        cudaGetSymbolAddress((void **)&p_W2_h, g_Wc2_h);
        cudaGetSymbolAddress((void **)&p_W2_l, g_Wc2_l);
        cudaFuncSetAttribute(hmma_gemm,
                             cudaFuncAttributeMaxDynamicSharedMemorySize, MMA_SMEM);
    }

    const int mma_grid = (N + 63) / 64;
    const int fin_grid  = (N * 32 + 255) / 256;
    const int edge_warp_grid = (E + 7) / 8;
    const int n4_agg = (N * HID) / 4;
    const int zero_grid = (n4_agg + 255) / 256;

    // order chosen so hmma_gemm (GEMM1) is the 6th launch (ncu -s 5 -c 1)
    k_prepW<<<(K_IN * HID + 255) / 256, 256>>>(W_emb, p_We_h, p_We_l, K_IN); // 0
    k_zero_deg<<<(N + 255) / 256, 256>>>(p_deg, N);                          // 1
    k_deg <<<(E + 255) / 256, 256>>>(ei, E);                                 // 2
    k_dinv<<<(N + 255) / 256, 256>>>(N);                                     // 3
    k_prepW<<<(HID * HID + 255) / 256, 256>>>(W_c1, p_W1_h, p_W1_l, HID);    // 4

    // h0 = x @ W_emb + b_emb                                                // 5
    hmma_gemm<<<mma_grid, 256, MMA_SMEM>>>(x, p_We_h, p_We_l, b_emb, nullptr,
                                           p_h, N, K_IN);
    k_prepW<<<(HID * HID + 255) / 256, 256>>>(W_c2, p_W2_h, p_W2_l, HID);

    // conv1
    hmma_gemm<<<mma_grid, 256, MMA_SMEM>>>(p_h, p_W1_h, p_W1_l, nullptr, p_dinv,
                                           p_hs, N, HID);
    k_zero4<<<zero_grid, 256>>>((float4 *)p_agg, n4_agg);
    k_scatter <<<edge_warp_grid, 256>>>(ei, E, p_hs, p_agg);
    k_finalize<<<fin_grid, 256>>>(p_agg, p_hs, p_dinv, b_c1, p_h, 1, N);

    // conv2
    hmma_gemm<<<mma_grid, 256, MMA_SMEM>>>(p_h, p_W2_h, p_W2_l, nullptr, p_dinv,
                                           p_hs, N, HID);
    k_zero4<<<zero_grid, 256>>>((float4 *)p_agg, n4_agg);
    k_scatter <<<edge_warp_grid, 256>>>(ei, E, p_hs, p_agg);
    k_finalize<<<fin_grid, 256>>>(p_agg, p_hs, p_dinv, b_c2, p_h, 0, N);

    // pool + head
    k_zero4<<<(NGRAPH * (HID + 1) / 4 + 255) / 256, 256>>>((float4 *)p_pool,
                                                           NGRAPH * (HID + 1) / 4);
    k_pool<<<(N + 7) / 8, 256>>>(batch, N, p_h, p_pool);
    k_head<<<NGRAPH, HID>>>(p_pool, W_l1, b_l1, W_l2, b_l2, out);
}

// round 9
// speedup vs baseline: 1.8648x; 1.3654x over previous
#include <cuda_runtime.h>
#include <cuda_bf16.h>
#include <cstdint>

#define NNODES  50000
#define MAXE    800000
#define HID     128
#define INDIM   768
#define NGRAPH  128
#define NCLS    3
#define NSCANB  196             // ceil(50000/256)

// GEMM tiling
#define BK      32
#define ASTRIDE 80
#define ABUF    5120
#define BBUF    10240
#define BUFSZ   30720
#define MMA_SMEM (2 * BUFSZ)

// ---------------- scratch -------------------------------------------------
__device__ float g_h   [NNODES * HID];
__device__ float g_hs  [NNODES * HID];
__device__ float g_dinv[NNODES];
__device__ int   g_deg [NNODES];
__device__ int   g_start[NNODES + 1];
__device__ int   g_cursor[NNODES];
__device__ int   g_bsum[NSCANB];
__device__ int   g_csr [MAXE];
__device__ float g_pool[NGRAPH * HID + NGRAPH];
__device__ __nv_bfloat16 g_Wemb_h[HID * INDIM], g_Wemb_l[HID * INDIM];
__device__ __nv_bfloat16 g_Wc1_h [HID * HID],   g_Wc1_l [HID * HID];
__device__ __nv_bfloat16 g_Wc2_h [HID * HID],   g_Wc2_l [HID * HID];

// ---------------- helpers -------------------------------------------------
__device__ __forceinline__ uint32_t s2u(const void *p) {
    uint32_t a;
    asm("{ .reg .u64 t; cvta.to.shared.u64 t, %1; cvt.u32.u64 %0, t; }"
        : "=r"(a) : "l"(p));
    return a;
}
__device__ __forceinline__ void red4(float *p, float4 v) {
    asm volatile("red.global.add.v4.f32 [%0], {%1, %2, %3, %4};"
                 :: "l"(p), "f"(v.x), "f"(v.y), "f"(v.z), "f"(v.w) : "memory");
}
__device__ __forceinline__ void ldsm4(uint32_t &r0, uint32_t &r1, uint32_t &r2,
                                      uint32_t &r3, uint32_t addr) {
    asm volatile("ldmatrix.sync.aligned.m8n8.x4.shared.b16 {%0,%1,%2,%3}, [%4];"
                 : "=r"(r0), "=r"(r1), "=r"(r2), "=r"(r3) : "r"(addr));
}
__device__ __forceinline__ void mma16816(float *c, const uint32_t *a,
                                         const uint32_t *b) {
    asm volatile(
        "mma.sync.aligned.m16n8k16.row.col.f32.bf16.bf16.f32 "
        "{%0,%1,%2,%3}, {%4,%5,%6,%7}, {%8,%9}, {%0,%1,%2,%3};"
        : "+f"(c[0]), "+f"(c[1]), "+f"(c[2]), "+f"(c[3])
        : "r"(a[0]), "r"(a[1]), "r"(a[2]), "r"(a[3]), "r"(b[0]), "r"(b[1]));
}
__device__ __forceinline__ void cpa16(uint32_t s, const void *g) {
    asm volatile("cp.async.cg.shared.global [%0], [%1], 16;" :: "r"(s), "l"(g));
}

// ---------------- misc small kernels --------------------------------------
__global__ void k_zero4(float4 *__restrict__ p, int n4) {
    int i = blockIdx.x * blockDim.x + threadIdx.x;
    if (i < n4) p[i] = make_float4(0.f, 0.f, 0.f, 0.f);
}
__global__ void k_zero_deg(int *__restrict__ p, int n) {
    int i = blockIdx.x * blockDim.x + threadIdx.x;
    if (i < n) p[i] = 0;
}
__global__ void k_deg(const int *__restrict__ ei, int E) {
    int i = blockIdx.x * blockDim.x + threadIdx.x;
    if (i < E) atomicAdd(&g_deg[ei[E + i]], 1);
}
__global__ void k_dinv(int N) {
    int i = blockIdx.x * blockDim.x + threadIdx.x;
    if (i < N) g_dinv[i] = rsqrtf((float)g_deg[i] + 1.0f);
}

// ---------------- CSR build: scan + fill ----------------------------------
__global__ void k_scan1(int N) {          // per-block exclusive scan of deg
    __shared__ int sh[256];
    int i = blockIdx.x * 256 + threadIdx.x;
    int v = (i < N) ? g_deg[i] : 0;
    sh[threadIdx.x] = v;
    __syncthreads();
    int x = v;
#pragma unroll
    for (int o = 1; o < 256; o <<= 1) {
        int y = (threadIdx.x >= o) ? sh[threadIdx.x - o] : 0;
        __syncthreads();
        x += y; sh[threadIdx.x] = x;
        __syncthreads();
    }
    if (i < N) g_start[i] = x - v;        // exclusive
    if (threadIdx.x == 255) g_bsum[blockIdx.x] = x;
}
__global__ void k_scan2() {               // scan of 196 block sums (1 block)
    __shared__ int sh[256];
    int v = (threadIdx.x < NSCANB) ? g_bsum[threadIdx.x] : 0;
    sh[threadIdx.x] = v;
    __syncthreads();
    int x = v;
#pragma unroll
    for (int o = 1; o < 256; o <<= 1) {
        int y = (threadIdx.x >= o) ? sh[threadIdx.x - o] : 0;
        __syncthreads();
        x += y; sh[threadIdx.x] = x;
        __syncthreads();
    }
    if (threadIdx.x < NSCANB) g_bsum[threadIdx.x] = x - v;   // exclusive
}
__global__ void k_scan3(int N, int E) {
    int i = blockIdx.x * 256 + threadIdx.x;
    if (i < N) {
        int s = g_start[i] + g_bsum[i >> 8];
        g_start[i] = s;
        g_cursor[i] = s;
    }
    if (i == 0) g_start[N] = E;
}
__global__ void k_fill(const int *__restrict__ ei, int E) {
    int i = blockIdx.x * blockDim.x + threadIdx.x;
    if (i >= E) return;
    int d = ei[E + i];
    int pos = atomicAdd(&g_cursor[d], 1);
    g_csr[pos] = ei[i];
}

// ---------------- W prep: split fp32 -> bf16 hi/lo, transpose to [N,K] ----
__global__ void k_prepW(const float *__restrict__ W, __nv_bfloat16 *__restrict__ Bh,
                        __nv_bfloat16 *__restrict__ Bl, int K) {
    int i = blockIdx.x * blockDim.x + threadIdx.x;
    if (i >= K * HID) return;
    int k = i / HID, n = i % HID;
    float v = W[i];
    __nv_bfloat16 h = __float2bfloat16(v);
    __nv_bfloat16 l = __float2bfloat16(v - __bfloat162float(h));
    Bh[(size_t)n * K + k] = h;
    Bl[(size_t)n * K + k] = l;
}

// ---------------- HMMA GEMM (double-buffered, cp.async) --------------------
__global__ void __launch_bounds__(256, 2)
hmma_gemm(const float *__restrict__ A,
          const __nv_bfloat16 *__restrict__ Bhg,
          const __nv_bfloat16 *__restrict__ Blg,
          const float *__restrict__ bias, const float *__restrict__ dinv,
          float *__restrict__ C, int M, int K)
{
    extern __shared__ __align__(1024) char smem[];
    const uint32_t sb = s2u(smem);
    const int tid = threadIdx.x;
    const int wid = tid >> 5, lane = tid & 31;
    const int warp_m = wid & 1, warp_n = wid >> 1;
    const int bm0 = blockIdx.x * 64;

    const int alr = tid >> 2, alq = tid & 3;
    int arow = bm0 + alr; if (arow >= M) arow = M - 1;
    const float *Ar = A + (size_t)arow * K + alq * 8;
    const uint32_t a_sts = (uint32_t)(alr * ASTRIDE + alq * 16);

    const int bln = tid >> 1, blu = tid & 1;
    const __nv_bfloat16 *Bhr = Bhg + (size_t)bln * K + blu * 16;
    const __nv_bfloat16 *Blr = Blg + (size_t)bln * K + blu * 16;
    const uint32_t b_sts = (uint32_t)(bln * ASTRIDE + blu * 32);

    const int sub = lane >> 3, lr8 = lane & 7;
    uint32_t a_off[2], b_off[2];
#pragma unroll
    for (int mi = 0; mi < 2; ++mi) {
        int row = warp_m * 32 + mi * 16 + ((sub & 1) << 3) + lr8;
        a_off[mi] = (uint32_t)(row * ASTRIDE + ((sub >> 1) << 4));
    }
#pragma unroll
    for (int np = 0; np < 2; ++np) {
        int nr = warp_n * 32 + np * 16 + ((sub >> 1) << 3) + lr8;
        b_off[np] = (uint32_t)(nr * ASTRIDE + ((sub & 1) << 4));
    }

    float acc[2][4][4];
#pragma unroll
    for (int mi = 0; mi < 2; ++mi)
#pragma unroll
        for (int ni = 0; ni < 4; ++ni)
#pragma unroll
            for (int q = 0; q < 4; ++q) acc[mi][ni][q] = 0.f;

    const int NC = K / BK;
    float4 va0, va1;

    va0 = *(const float4 *)(Ar);
    va1 = *(const float4 *)(Ar + 4);
    {
        uint32_t s0 = sb + 2 * ABUF + b_sts;
        cpa16(s0,             Bhr);
        cpa16(s0 + 16,        Bhr + 8);
        cpa16(s0 + BBUF,      Blr);
        cpa16(s0 + BBUF + 16, Blr + 8);
        asm volatile("cp.async.commit_group;" ::: "memory");
    }
    {
        __nv_bfloat162 h0 = __floats2bfloat162_rn(va0.x, va0.y);
        __nv_bfloat162 h1 = __floats2bfloat162_rn(va0.z, va0.w);
        __nv_bfloat162 h2 = __floats2bfloat162_rn(va1.x, va1.y);
        __nv_bfloat162 h3 = __floats2bfloat162_rn(va1.z, va1.w);
        __nv_bfloat162 l0 = __floats2bfloat162_rn(va0.x - __bfloat162float(h0.x), va0.y - __bfloat162float(h0.y));
        __nv_bfloat162 l1 = __floats2bfloat162_rn(va0.z - __bfloat162float(h1.x), va0.w - __bfloat162float(h1.y));
        __nv_bfloat162 l2 = __floats2bfloat162_rn(va1.x - __bfloat162float(h2.x), va1.y - __bfloat162float(h2.y));
        __nv_bfloat162 l3 = __floats2bfloat162_rn(va1.z - __bfloat162float(h3.x), va1.w - __bfloat162float(h3.y));
        *(uint4 *)(smem + a_sts) =
            make_uint4(*(uint32_t *)&h0, *(uint32_t *)&h1, *(uint32_t *)&h2, *(uint32_t *)&h3);
        *(uint4 *)(smem + ABUF + a_sts) =
            make_uint4(*(uint32_t *)&l0, *(uint32_t *)&l1, *(uint32_t *)&l2, *(uint32_t *)&l3);
    }
    asm volatile("cp.async.wait_group 0;" ::: "memory");
    __syncthreads();

    for (int c = 0; c < NC; ++c) {
        const uint32_t bo = (c & 1) ? (uint32_t)BUFSZ : 0u;
        const uint32_t bn = (c & 1) ? 0u : (uint32_t)BUFSZ;
        const bool more = (c + 1 < NC);
        if (more) {
            const int k1 = (c + 1) * BK;
            va0 = *(const float4 *)(Ar + k1);
            va1 = *(const float4 *)(Ar + k1 + 4);
            uint32_t s0 = sb + bn + 2 * ABUF + b_sts;
            cpa16(s0,             Bhr + k1);
            cpa16(s0 + 16,        Bhr + k1 + 8);
            cpa16(s0 + BBUF,      Blr + k1);
            cpa16(s0 + BBUF + 16, Blr + k1 + 8);
            asm volatile("cp.async.commit_group;" ::: "memory");
        }

#pragma unroll
        for (int ks = 0; ks < 2; ++ks) {
            uint32_t ahi[2][4], alo[2][4], bhi[4][2], blo[4][2];
#pragma unroll
            for (int mi = 0; mi < 2; ++mi) {
                uint32_t ad = sb + bo + a_off[mi] + ks * 32;
                ldsm4(ahi[mi][0], ahi[mi][1], ahi[mi][2], ahi[mi][3], ad);
                ldsm4(alo[mi][0], alo[mi][1], alo[mi][2], alo[mi][3], ad + ABUF);
            }
#pragma unroll
            for (int np = 0; np < 2; ++np) {
                uint32_t bd = sb + bo + 2 * ABUF + b_off[np] + ks * 32;
                ldsm4(bhi[np * 2][0], bhi[np * 2][1],
                      bhi[np * 2 + 1][0], bhi[np * 2 + 1][1], bd);
                ldsm4(blo[np * 2][0], blo[np * 2][1],
                      blo[np * 2 + 1][0], blo[np * 2 + 1][1], bd + BBUF);
            }
#pragma unroll
            for (int mi = 0; mi < 2; ++mi)
#pragma unroll
                for (int ni = 0; ni < 4; ++ni) {
                    mma16816(acc[mi][ni], ahi[mi], bhi[ni]);
                    mma16816(acc[mi][ni], ahi[mi], blo[ni]);
                    mma16816(acc[mi][ni], alo[mi], bhi[ni]);
                }
        }

        if (more) {
            __nv_bfloat162 h0 = __floats2bfloat162_rn(va0.x, va0.y);
            __nv_bfloat162 h1 = __floats2bfloat162_rn(va0.z, va0.w);
            __nv_bfloat162 h2 = __floats2bfloat162_rn(va1.x, va1.y);
            __nv_bfloat162 h3 = __floats2bfloat162_rn(va1.z, va1.w);
            __nv_bfloat162 l0 = __floats2bfloat162_rn(va0.x - __bfloat162float(h0.x), va0.y - __bfloat162float(h0.y));
            __nv_bfloat162 l1 = __floats2bfloat162_rn(va0.z - __bfloat162float(h1.x), va0.w - __bfloat162float(h1.y));
            __nv_bfloat162 l2 = __floats2bfloat162_rn(va1.x - __bfloat162float(h2.x), va1.y - __bfloat162float(h2.y));
            __nv_bfloat162 l3 = __floats2bfloat162_rn(va1.z - __bfloat162float(h3.x), va1.w - __bfloat162float(h3.y));
            *(uint4 *)(smem + bn + a_sts) =
                make_uint4(*(uint32_t *)&h0, *(uint32_t *)&h1, *(uint32_t *)&h2, *(uint32_t *)&h3);
            *(uint4 *)(smem + bn + ABUF + a_sts) =
                make_uint4(*(uint32_t *)&l0, *(uint32_t *)&l1, *(uint32_t *)&l2, *(uint32_t *)&l3);
            asm volatile("cp.async.wait_group 0;" ::: "memory");
        }
        __syncthreads();
    }

    const int gid = lane >> 2, qid = lane & 3;
#pragma unroll
    for (int mi = 0; mi < 2; ++mi) {
        int row0 = bm0 + warp_m * 32 + mi * 16 + gid;
        int row1 = row0 + 8;
        float s0 = 1.f, s1 = 1.f;
        if (dinv) {
            if (row0 < M) s0 = dinv[row0];
            if (row1 < M) s1 = dinv[row1];
        }
#pragma unroll
        for (int ni = 0; ni < 4; ++ni) {
            int col = warp_n * 32 + ni * 8 + qid * 2;
            float b0 = 0.f, b1 = 0.f;
            if (bias) { b0 = bias[col]; b1 = bias[col + 1]; }
            if (row0 < M) {
                float2 o = make_float2(fmaf(acc[mi][ni][0], s0, b0),
                                       fmaf(acc[mi][ni][1], s0, b1));
                *(float2 *)&C[(size_t)row0 * HID + col] = o;
            }
            if (row1 < M) {
                float2 o = make_float2(fmaf(acc[mi][ni][2], s1, b0),
                                       fmaf(acc[mi][ni][3], s1, b1));
                *(float2 *)&C[(size_t)row1 * HID + col] = o;
            }
        }
    }
}

// ---------------- CSR aggregate: warp per node -----------------------------
// out[d] = dinv[d]*(sum_{s in csr[d]} hs[s] + hs[d]) + bias  (opt relu)
__global__ void __launch_bounds__(256)
k_agg(const float *__restrict__ hs, const float *__restrict__ bias,
      float *__restrict__ outp, int relu, int N)
{
    int node = (blockIdx.x * blockDim.x + threadIdx.x) >> 5;
    if (node >= N) return;
    int lane = threadIdx.x & 31;
    int c = lane * 4;

    int e0 = g_start[node], e1 = g_start[node + 1];
    float4 acc = *(const float4 *)&hs[(size_t)node * HID + c];   // self loop

    int e = e0;
    for (; e + 4 <= e1; e += 4) {
        int i0 = g_csr[e], i1 = g_csr[e + 1], i2 = g_csr[e + 2], i3 = g_csr[e + 3];
        float4 v0 = *(const float4 *)&hs[(size_t)i0 * HID + c];
        float4 v1 = *(const float4 *)&hs[(size_t)i1 * HID + c];
        float4 v2 = *(const float4 *)&hs[(size_t)i2 * HID + c];
        float4 v3 = *(const float4 *)&hs[(size_t)i3 * HID + c];
        acc.x += v0.x + v1.x + v2.x + v3.x;
        acc.y += v0.y + v1.y + v2.y + v3.y;
        acc.z += v0.z + v1.z + v2.z + v3.z;
        acc.w += v0.w + v1.w + v2.w + v3.w;
    }
    for (; e < e1; ++e) {
        int i0 = g_csr[e];
        float4 v0 = *(const float4 *)&hs[(size_t)i0 * HID + c];
        acc.x += v0.x; acc.y += v0.y; acc.z += v0.z; acc.w += v0.w;
    }

    float dv = g_dinv[node];
    float4 b = *(const float4 *)&bias[c];
    float4 o;
    o.x = fmaf(dv, acc.x, b.x);
    o.y = fmaf(dv, acc.y, b.y);
    o.z = fmaf(dv, acc.z, b.z);
    o.w = fmaf(dv, acc.w, b.w);
    if (relu) {
        o.x = fmaxf(o.x, 0.f); o.y = fmaxf(o.y, 0.f);
        o.z = fmaxf(o.z, 0.f); o.w = fmaxf(o.w, 0.f);
    }
    *(float4 *)&outp[(size_t)node * HID + c] = o;
}

// ---------------- pooling / head ------------------------------------------
__global__ void k_pool(const int *__restrict__ batch, int N,
                       const float *__restrict__ h, float *__restrict__ pool)
{
    int w = (blockIdx.x * blockDim.x + threadIdx.x) >> 5;
    if (w >= N) return;
    int lane = threadIdx.x & 31;
    int b = batch[w];
    float4 v = *(const float4 *)&h[(size_t)w * HID + lane * 4];
    red4(&pool[(size_t)b * HID + lane * 4], v);
    if (lane == 0) atomicAdd(&pool[NGRAPH * HID + b], 1.0f);
}
__global__ void k_head(const float *__restrict__ pool,
                       const float *__restrict__ W1, const float *__restrict__ b1,
                       const float *__restrict__ W2, const float *__restrict__ b2,
                       float *__restrict__ out)
{
    __shared__ float gv[HID];
    __shared__ float hid[HID];
    int g = blockIdx.x, t = threadIdx.x;
    float cnt = fmaxf(pool[NGRAPH * HID + g], 1.0f);
    gv[t] = pool[(size_t)g * HID + t] / cnt;
    __syncthreads();
    float acc = b1[t];
#pragma unroll 8
    for (int c = 0; c < HID; ++c) acc = fmaf(gv[c], W1[c * HID + t], acc);
    hid[t] = fmaxf(acc, 0.f);
    __syncthreads();
    if (t < NCLS) {
        float o = b2[t];
#pragma unroll 8
        for (int hh = 0; hh < HID; ++hh) o = fmaf(hid[hh], W2[hh * NCLS + t], o);
        out[g * NCLS + t] = o;
    }
}

// ---------------- launcher -------------------------------------------------
extern "C" void kernel_launch(void *const *d_in, const int *in_sizes, int n_in,
                              void *d_out, int out_size)
{
    const float *x     = (const float *)d_in[0];
    const int   *ei    = (const int *)d_in[1];
    const int   *batch = (const int *)d_in[2];
    const float *W_emb = (const float *)d_in[3], *b_emb = (const float *)d_in[4];
    const float *W_c1  = (const float *)d_in[5], *b_c1  = (const float *)d_in[6];
    const float *W_c2  = (const float *)d_in[7], *b_c2  = (const float *)d_in[8];
    const float *W_l1  = (const float *)d_in[9], *b_l1  = (const float *)d_in[10];
    const float *W_l2  = (const float *)d_in[11], *b_l2 = (const float *)d_in[12];
    float *out = (float *)d_out;

    const int E = in_sizes[1] / 2;
    const int N = in_sizes[2];
    const int K_IN = in_sizes[0] / N;

    static float *p_h = nullptr, *p_hs = nullptr, *p_dinv = nullptr,
                 *p_pool = nullptr;
    static int *p_deg = nullptr;
    static __nv_bfloat16 *p_We_h, *p_We_l, *p_W1_h, *p_W1_l, *p_W2_h, *p_W2_l;
    if (!p_h) {
        cudaGetSymbolAddress((void **)&p_h,    g_h);
        cudaGetSymbolAddress((void **)&p_hs,   g_hs);
        cudaGetSymbolAddress((void **)&p_dinv, g_dinv);
        cudaGetSymbolAddress((void **)&p_pool, g_pool);
        cudaGetSymbolAddress((void **)&p_deg,  g_deg);
        cudaGetSymbolAddress((void **)&p_We_h, g_Wemb_h);
        cudaGetSymbolAddress((void **)&p_We_l, g_Wemb_l);
        cudaGetSymbolAddress((void **)&p_W1_h, g_Wc1_h);
        cudaGetSymbolAddress((void **)&p_W1_l, g_Wc1_l);
        cudaGetSymbolAddress((void **)&p_W2_h, g_Wc2_h);
        cudaGetSymbolAddress((void **)&p_W2_l, g_Wc2_l);
        cudaFuncSetAttribute(hmma_gemm,
                             cudaFuncAttributeMaxDynamicSharedMemorySize, MMA_SMEM);
    }

    const int mma_grid  = (N + 63) / 64;
    const int agg_grid  = (N * 32 + 255) / 256;

    // launch order: hmma_gemm (GEMM1) at index 3 (profiled slot last rounds)
    k_prepW<<<(K_IN * HID + 255) / 256, 256>>>(W_emb, p_We_h, p_We_l, K_IN); // 0
    k_zero_deg<<<(N + 255) / 256, 256>>>(p_deg, N);                          // 1
    k_deg <<<(E + 255) / 256, 256>>>(ei, E);                                 // 2
    hmma_gemm<<<mma_grid, 256, MMA_SMEM>>>(x, p_We_h, p_We_l, b_emb, nullptr,
                                           p_h, N, K_IN);                    // 3
    k_dinv<<<(N + 255) / 256, 256>>>(N);                                     // 4
    k_prepW<<<(HID * HID + 255) / 256, 256>>>(W_c1, p_W1_h, p_W1_l, HID);    // 5
    k_prepW<<<(HID * HID + 255) / 256, 256>>>(W_c2, p_W2_h, p_W2_l, HID);

    // CSR build
    k_scan1<<<NSCANB, 256>>>(N);
    k_scan2<<<1, 256>>>();
    k_scan3<<<(N + 255) / 256, 256>>>(N, E);
    k_fill <<<(E + 255) / 256, 256>>>(ei, E);

    // conv1
    hmma_gemm<<<mma_grid, 256, MMA_SMEM>>>(p_h, p_W1_h, p_W1_l, nullptr, p_dinv,
                                           p_hs, N, HID);
    k_agg<<<agg_grid, 256>>>(p_hs, b_c1, p_h, 1, N);

    // conv2
    hmma_gemm<<<mma_grid, 256, MMA_SMEM>>>(p_h, p_W2_h, p_W2_l, nullptr, p_dinv,
                                           p_hs, N, HID);
    k_agg<<<agg_grid, 256>>>(p_hs, b_c2, p_h, 0, N);

    // pool + head
    k_zero4<<<(NGRAPH * (HID + 1) / 4 + 255) / 256, 256>>>((float4 *)p_pool,
                                                           NGRAPH * (HID + 1) / 4);
    k_pool<<<(N + 7) / 8, 256>>>(batch, N, p_h, p_pool);
    k_head<<<NGRAPH, HID>>>(p_pool, W_l1, b_l1, W_l2, b_l2, out);
}

// round 10
// speedup vs baseline: 2.0188x; 1.0826x over previous
#include <cuda_runtime.h>
#include <cuda_bf16.h>
#include <cstdint>

#define NNODES  50000
#define MAXE    800000
#define HID     128
#define INDIM   768
#define NGRAPH  128
#define NCLS    3
#define NSCANB  196             // ceil(50000/256)

// GEMM tiling: BM=128, BN=128, BK=32
#define BK      32
#define ASTRIDE 80
#define ABUF    10240           // 128 * 80
#define BBUF    10240
#define BUFSZ   40960           // 2*ABUF + 2*BBUF
#define MMA_SMEM (2 * BUFSZ)    // 81920

// ---------------- scratch -------------------------------------------------
__device__ float g_h   [NNODES * HID];
__device__ float g_hs  [NNODES * HID];
__device__ float g_dinv[NNODES];
__device__ int   g_deg [NNODES];
__device__ int   g_start[NNODES + 1];
__device__ int   g_cursor[NNODES];
__device__ int   g_bsum[NSCANB];
__device__ int   g_csr [MAXE];
__device__ float g_pool[NGRAPH * HID + NGRAPH];
__device__ __nv_bfloat16 g_Wemb_h[HID * INDIM], g_Wemb_l[HID * INDIM];
__device__ __nv_bfloat16 g_Wc1_h [HID * HID],   g_Wc1_l [HID * HID];
__device__ __nv_bfloat16 g_Wc2_h [HID * HID],   g_Wc2_l [HID * HID];

// ---------------- helpers -------------------------------------------------
__device__ __forceinline__ uint32_t s2u(const void *p) {
    uint32_t a;
    asm("{ .reg .u64 t; cvta.to.shared.u64 t, %1; cvt.u32.u64 %0, t; }"
        : "=r"(a) : "l"(p));
    return a;
}
__device__ __forceinline__ void red4(float *p, float4 v) {
    asm volatile("red.global.add.v4.f32 [%0], {%1, %2, %3, %4};"
                 :: "l"(p), "f"(v.x), "f"(v.y), "f"(v.z), "f"(v.w) : "memory");
}
__device__ __forceinline__ void ldsm4(uint32_t &r0, uint32_t &r1, uint32_t &r2,
                                      uint32_t &r3, uint32_t addr) {
    asm volatile("ldmatrix.sync.aligned.m8n8.x4.shared.b16 {%0,%1,%2,%3}, [%4];"
                 : "=r"(r0), "=r"(r1), "=r"(r2), "=r"(r3) : "r"(addr));
}
__device__ __forceinline__ void mma16816(float *c, const uint32_t *a,
                                         const uint32_t *b) {
    asm volatile(
        "mma.sync.aligned.m16n8k16.row.col.f32.bf16.bf16.f32 "
        "{%0,%1,%2,%3}, {%4,%5,%6,%7}, {%8,%9}, {%0,%1,%2,%3};"
        : "+f"(c[0]), "+f"(c[1]), "+f"(c[2]), "+f"(c[3])
        : "r"(a[0]), "r"(a[1]), "r"(a[2]), "r"(a[3]), "r"(b[0]), "r"(b[1]));
}
__device__ __forceinline__ void cpa16(uint32_t s, const void *g) {
    asm volatile("cp.async.cg.shared.global [%0], [%1], 16;" :: "r"(s), "l"(g));
}
__device__ __forceinline__ void cvt8(const float4 &v0, const float4 &v1,
                                     uint4 &hv, uint4 &lv) {
    __nv_bfloat162 h0 = __floats2bfloat162_rn(v0.x, v0.y);
    __nv_bfloat162 h1 = __floats2bfloat162_rn(v0.z, v0.w);
    __nv_bfloat162 h2 = __floats2bfloat162_rn(v1.x, v1.y);
    __nv_bfloat162 h3 = __floats2bfloat162_rn(v1.z, v1.w);
    __nv_bfloat162 l0 = __floats2bfloat162_rn(v0.x - __bfloat162float(h0.x),
                                              v0.y - __bfloat162float(h0.y));
    __nv_bfloat162 l1 = __floats2bfloat162_rn(v0.z - __bfloat162float(h1.x),
                                              v0.w - __bfloat162float(h1.y));
    __nv_bfloat162 l2 = __floats2bfloat162_rn(v1.x - __bfloat162float(h2.x),
                                              v1.y - __bfloat162float(h2.y));
    __nv_bfloat162 l3 = __floats2bfloat162_rn(v1.z - __bfloat162float(h3.x),
                                              v1.w - __bfloat162float(h3.y));
    hv = make_uint4(*(uint32_t *)&h0, *(uint32_t *)&h1,
                    *(uint32_t *)&h2, *(uint32_t *)&h3);
    lv = make_uint4(*(uint32_t *)&l0, *(uint32_t *)&l1,
                    *(uint32_t *)&l2, *(uint32_t *)&l3);
}

// ---------------- misc small kernels --------------------------------------
__global__ void k_zero4(float4 *__restrict__ p, int n4) {
    int i = blockIdx.x * blockDim.x + threadIdx.x;
    if (i < n4) p[i] = make_float4(0.f, 0.f, 0.f, 0.f);
}
__global__ void k_zero_deg(int *__restrict__ p, int n) {
    int i = blockIdx.x * blockDim.x + threadIdx.x;
    if (i < n) p[i] = 0;
}
__global__ void k_deg(const int *__restrict__ ei, int E) {
    int i = blockIdx.x * blockDim.x + threadIdx.x;
    if (i < E) atomicAdd(&g_deg[ei[E + i]], 1);
}
__global__ void k_dinv(int N) {
    int i = blockIdx.x * blockDim.x + threadIdx.x;
    if (i < N) g_dinv[i] = rsqrtf((float)g_deg[i] + 1.0f);
}

// ---------------- CSR build: scan + fill ----------------------------------
__global__ void k_scan1(int N) {
    __shared__ int sh[256];
    int i = blockIdx.x * 256 + threadIdx.x;
    int v = (i < N) ? g_deg[i] : 0;
    sh[threadIdx.x] = v;
    __syncthreads();
    int x = v;
#pragma unroll
    for (int o = 1; o < 256; o <<= 1) {
        int y = (threadIdx.x >= o) ? sh[threadIdx.x - o] : 0;
        __syncthreads();
        x += y; sh[threadIdx.x] = x;
        __syncthreads();
    }
    if (i < N) g_start[i] = x - v;
    if (threadIdx.x == 255) g_bsum[blockIdx.x] = x;
}
__global__ void k_scan2() {
    __shared__ int sh[256];
    int v = (threadIdx.x < NSCANB) ? g_bsum[threadIdx.x] : 0;
    sh[threadIdx.x] = v;
    __syncthreads();
    int x = v;
#pragma unroll
    for (int o = 1; o < 256; o <<= 1) {
        int y = (threadIdx.x >= o) ? sh[threadIdx.x - o] : 0;
        __syncthreads();
        x += y; sh[threadIdx.x] = x;
        __syncthreads();
    }
    if (threadIdx.x < NSCANB) g_bsum[threadIdx.x] = x - v;
}
__global__ void k_scan3(int N, int E) {
    int i = blockIdx.x * 256 + threadIdx.x;
    if (i < N) {
        int s = g_start[i] + g_bsum[i >> 8];
        g_start[i] = s;
        g_cursor[i] = s;
    }
    if (i == 0) g_start[N] = E;
}
__global__ void k_fill(const int *__restrict__ ei, int E) {
    int i = blockIdx.x * blockDim.x + threadIdx.x;
    if (i >= E) return;
    int d = ei[E + i];
    int pos = atomicAdd(&g_cursor[d], 1);
    g_csr[pos] = ei[i];
}

// ---------------- W prep --------------------------------------------------
__global__ void k_prepW(const float *__restrict__ W, __nv_bfloat16 *__restrict__ Bh,
                        __nv_bfloat16 *__restrict__ Bl, int K) {
    int i = blockIdx.x * blockDim.x + threadIdx.x;
    if (i >= K * HID) return;
    int k = i / HID, n = i % HID;
    float v = W[i];
    __nv_bfloat16 h = __float2bfloat16(v);
    __nv_bfloat16 l = __float2bfloat16(v - __bfloat162float(h));
    Bh[(size_t)n * K + k] = h;
    Bl[(size_t)n * K + k] = l;
}

// ---------------- HMMA GEMM (BM=128, double-buffered, cp.async) ------------
// warps: 4m x 2n; warp tile m32 n64.
// per-buffer: Ahi[0,10240) Alo[10240,20480) Bhi[20480,30720) Blo[30720,40960)
__global__ void __launch_bounds__(256, 2)
hmma_gemm(const float *__restrict__ A,
          const __nv_bfloat16 *__restrict__ Bhg,
          const __nv_bfloat16 *__restrict__ Blg,
          const float *__restrict__ bias, const float *__restrict__ dinv,
          float *__restrict__ C, int M, int K)
{
    extern __shared__ __align__(1024) char smem[];
    const uint32_t sb = s2u(smem);
    const int tid = threadIdx.x;
    const int wid = tid >> 5, lane = tid & 31;
    const int warp_m = wid & 3, warp_n = wid >> 2;
    const int bm0 = blockIdx.x * 128;

    // A loader: row = tid>>1 (0..127), half = tid&1 (16 floats each)
    const int alr = tid >> 1, alq = tid & 1;
    int arow = bm0 + alr; if (arow >= M) arow = M - 1;
    const float *Ar = A + (size_t)arow * K + alq * 16;
    const uint32_t a_sts = (uint32_t)(alr * ASTRIDE + alq * 32);

    // B loader: n = tid>>1 (0..127), half = tid&1 (16 bf16 each)
    const int bln = tid >> 1, blu = tid & 1;
    const __nv_bfloat16 *Bhr = Bhg + (size_t)bln * K + blu * 16;
    const __nv_bfloat16 *Blr = Blg + (size_t)bln * K + blu * 16;
    const uint32_t b_sts = (uint32_t)(bln * ASTRIDE + blu * 32);

    // fragment lane offsets
    const int sub = lane >> 3, lr8 = lane & 7;
    uint32_t a_off[2], b_off[4];
#pragma unroll
    for (int mi = 0; mi < 2; ++mi) {
        int row = warp_m * 32 + mi * 16 + ((sub & 1) << 3) + lr8;
        a_off[mi] = (uint32_t)(row * ASTRIDE + ((sub >> 1) << 4));
    }
#pragma unroll
    for (int np = 0; np < 4; ++np) {
        int nr = warp_n * 64 + np * 16 + ((sub >> 1) << 3) + lr8;
        b_off[np] = (uint32_t)(nr * ASTRIDE + ((sub & 1) << 4));
    }

    float acc[2][8][4];
#pragma unroll
    for (int mi = 0; mi < 2; ++mi)
#pragma unroll
        for (int ni = 0; ni < 8; ++ni)
#pragma unroll
            for (int q = 0; q < 4; ++q) acc[mi][ni][q] = 0.f;

    const int NC = K / BK;
    float4 va0, va1, va2, va3;

    // ---- prologue ----
    va0 = *(const float4 *)(Ar);
    va1 = *(const float4 *)(Ar + 4);
    va2 = *(const float4 *)(Ar + 8);
    va3 = *(const float4 *)(Ar + 12);
    {
        uint32_t s0 = sb + 2 * ABUF + b_sts;
        cpa16(s0,             Bhr);
        cpa16(s0 + 16,        Bhr + 8);
        cpa16(s0 + BBUF,      Blr);
        cpa16(s0 + BBUF + 16, Blr + 8);
        asm volatile("cp.async.commit_group;" ::: "memory");
    }
    {
        uint4 hv, lv;
        cvt8(va0, va1, hv, lv);
        *(uint4 *)(smem + a_sts)        = hv;
        *(uint4 *)(smem + ABUF + a_sts) = lv;
        cvt8(va2, va3, hv, lv);
        *(uint4 *)(smem + a_sts + 16)        = hv;
        *(uint4 *)(smem + ABUF + a_sts + 16) = lv;
    }
    asm volatile("cp.async.wait_group 0;" ::: "memory");
    __syncthreads();

    for (int c = 0; c < NC; ++c) {
        const uint32_t bo = (c & 1) ? (uint32_t)BUFSZ : 0u;
        const uint32_t bn = (c & 1) ? 0u : (uint32_t)BUFSZ;
        const bool more = (c + 1 < NC);
        if (more) {
            const int k1 = (c + 1) * BK;
            va0 = *(const float4 *)(Ar + k1);
            va1 = *(const float4 *)(Ar + k1 + 4);
            va2 = *(const float4 *)(Ar + k1 + 8);
            va3 = *(const float4 *)(Ar + k1 + 12);
            uint32_t s0 = sb + bn + 2 * ABUF + b_sts;
            cpa16(s0,             Bhr + k1);
            cpa16(s0 + 16,        Bhr + k1 + 8);
            cpa16(s0 + BBUF,      Blr + k1);
            cpa16(s0 + BBUF + 16, Blr + k1 + 8);
            asm volatile("cp.async.commit_group;" ::: "memory");
        }

#pragma unroll
        for (int ks = 0; ks < 2; ++ks) {
            uint32_t ahi[2][4], alo[2][4];
#pragma unroll
            for (int mi = 0; mi < 2; ++mi) {
                uint32_t ad = sb + bo + a_off[mi] + ks * 32;
                ldsm4(ahi[mi][0], ahi[mi][1], ahi[mi][2], ahi[mi][3], ad);
                ldsm4(alo[mi][0], alo[mi][1], alo[mi][2], alo[mi][3], ad + ABUF);
            }
#pragma unroll
            for (int np = 0; np < 4; ++np) {
                uint32_t bhi[2][2], blo[2][2];
                uint32_t bd = sb + bo + 2 * ABUF + b_off[np] + ks * 32;
                ldsm4(bhi[0][0], bhi[0][1], bhi[1][0], bhi[1][1], bd);
                ldsm4(blo[0][0], blo[0][1], blo[1][0], blo[1][1], bd + BBUF);
#pragma unroll
                for (int mi = 0; mi < 2; ++mi)
#pragma unroll
                    for (int h = 0; h < 2; ++h) {
                        float *ac = acc[mi][np * 2 + h];
                        mma16816(ac, ahi[mi], bhi[h]);
                        mma16816(ac, ahi[mi], blo[h]);
                        mma16816(ac, alo[mi], bhi[h]);
                    }
            }
        }

        if (more) {
            uint4 hv, lv;
            cvt8(va0, va1, hv, lv);
            *(uint4 *)(smem + bn + a_sts)        = hv;
            *(uint4 *)(smem + bn + ABUF + a_sts) = lv;
            cvt8(va2, va3, hv, lv);
            *(uint4 *)(smem + bn + a_sts + 16)        = hv;
            *(uint4 *)(smem + bn + ABUF + a_sts + 16) = lv;
            asm volatile("cp.async.wait_group 0;" ::: "memory");
        }
        __syncthreads();
    }

    // ---- epilogue ----
    const int gid = lane >> 2, qid = lane & 3;
#pragma unroll
    for (int mi = 0; mi < 2; ++mi) {
        int row0 = bm0 + warp_m * 32 + mi * 16 + gid;
        int row1 = row0 + 8;
        float s0 = 1.f, s1 = 1.f;
        if (dinv) {
            if (row0 < M) s0 = dinv[row0];
            if (row1 < M) s1 = dinv[row1];
        }
#pragma unroll
        for (int ni = 0; ni < 8; ++ni) {
            int col = warp_n * 64 + ni * 8 + qid * 2;
            float b0 = 0.f, b1 = 0.f;
            if (bias) { b0 = bias[col]; b1 = bias[col + 1]; }
            if (row0 < M) {
                float2 o = make_float2(fmaf(acc[mi][ni][0], s0, b0),
                                       fmaf(acc[mi][ni][1], s0, b1));
                *(float2 *)&C[(size_t)row0 * HID + col] = o;
            }
            if (row1 < M) {
                float2 o = make_float2(fmaf(acc[mi][ni][2], s1, b0),
                                       fmaf(acc[mi][ni][3], s1, b1));
                *(float2 *)&C[(size_t)row1 * HID + col] = o;
            }
        }
    }
}

// ---------------- CSR aggregate: warp per node -----------------------------
__global__ void __launch_bounds__(256)
k_agg(const float *__restrict__ hs, const float *__restrict__ bias,
      float *__restrict__ outp, int relu, int N)
{
    int node = (blockIdx.x * blockDim.x + threadIdx.x) >> 5;
    if (node >= N) return;
    int lane = threadIdx.x & 31;
    int c = lane * 4;

    int e0 = g_start[node], e1 = g_start[node + 1];
    float4 acc = *(const float4 *)&hs[(size_t)node * HID + c];

    int e = e0;
    for (; e + 4 <= e1; e += 4) {
        int i0 = g_csr[e], i1 = g_csr[e + 1], i2 = g_csr[e + 2], i3 = g_csr[e + 3];
        float4 v0 = *(const float4 *)&hs[(size_t)i0 * HID + c];
        float4 v1 = *(const float4 *)&hs[(size_t)i1 * HID + c];
        float4 v2 = *(const float4 *)&hs[(size_t)i2 * HID + c];
        float4 v3 = *(const float4 *)&hs[(size_t)i3 * HID + c];
        acc.x += v0.x + v1.x + v2.x + v3.x;
        acc.y += v0.y + v1.y + v2.y + v3.y;
        acc.z += v0.z + v1.z + v2.z + v3.z;
        acc.w += v0.w + v1.w + v2.w + v3.w;
    }
    for (; e < e1; ++e) {
        int i0 = g_csr[e];
        float4 v0 = *(const float4 *)&hs[(size_t)i0 * HID + c];
        acc.x += v0.x; acc.y += v0.y; acc.z += v0.z; acc.w += v0.w;
    }

    float dv = g_dinv[node];
    float4 b = *(const float4 *)&bias[c];
    float4 o;
    o.x = fmaf(dv, acc.x, b.x);
    o.y = fmaf(dv, acc.y, b.y);
    o.z = fmaf(dv, acc.z, b.z);
    o.w = fmaf(dv, acc.w, b.w);
    if (relu) {
        o.x = fmaxf(o.x, 0.f); o.y = fmaxf(o.y, 0.f);
        o.z = fmaxf(o.z, 0.f); o.w = fmaxf(o.w, 0.f);
    }
    *(float4 *)&outp[(size_t)node * HID + c] = o;
}

// ---------------- pooling / head ------------------------------------------
__global__ void k_pool(const int *__restrict__ batch, int N,
                       const float *__restrict__ h, float *__restrict__ pool)
{
    int w = (blockIdx.x * blockDim.x + threadIdx.x) >> 5;
    if (w >= N) return;
    int lane = threadIdx.x & 31;
    int b = batch[w];
    float4 v = *(const float4 *)&h[(size_t)w * HID + lane * 4];
    red4(&pool[(size_t)b * HID + lane * 4], v);
    if (lane == 0) atomicAdd(&pool[NGRAPH * HID + b], 1.0f);
}
__global__ void k_head(const float *__restrict__ pool,
                       const float *__restrict__ W1, const float *__restrict__ b1,
                       const float *__restrict__ W2, const float *__restrict__ b2,
                       float *__restrict__ out)
{
    __shared__ float gv[HID];
    __shared__ float hid[HID];
    int g = blockIdx.x, t = threadIdx.x;
    float cnt = fmaxf(pool[NGRAPH * HID + g], 1.0f);
    gv[t] = pool[(size_t)g * HID + t] / cnt;
    __syncthreads();
    float acc = b1[t];
#pragma unroll 8
    for (int c = 0; c < HID; ++c) acc = fmaf(gv[c], W1[c * HID + t], acc);
    hid[t] = fmaxf(acc, 0.f);
    __syncthreads();
    if (t < NCLS) {
        float o = b2[t];
#pragma unroll 8
        for (int hh = 0; hh < HID; ++hh) o = fmaf(hid[hh], W2[hh * NCLS + t], o);
        out[g * NCLS + t] = o;
    }
}

// ---------------- launcher -------------------------------------------------
extern "C" void kernel_launch(void *const *d_in, const int *in_sizes, int n_in,
                              void *d_out, int out_size)
{
    const float *x     = (const float *)d_in[0];
    const int   *ei    = (const int *)d_in[1];
    const int   *batch = (const int *)d_in[2];
    const float *W_emb = (const float *)d_in[3], *b_emb = (const float *)d_in[4];
    const float *W_c1  = (const float *)d_in[5], *b_c1  = (const float *)d_in[6];
    const float *W_c2  = (const float *)d_in[7], *b_c2  = (const float *)d_in[8];
    const float *W_l1  = (const float *)d_in[9], *b_l1  = (const float *)d_in[10];
    const float *W_l2  = (const float *)d_in[11], *b_l2 = (const float *)d_in[12];
    float *out = (float *)d_out;

    const int E = in_sizes[1] / 2;
    const int N = in_sizes[2];
    const int K_IN = in_sizes[0] / N;

    static float *p_h = nullptr, *p_hs = nullptr, *p_dinv = nullptr,
                 *p_pool = nullptr;
    static int *p_deg = nullptr;
    static __nv_bfloat16 *p_We_h, *p_We_l, *p_W1_h, *p_W1_l, *p_W2_h, *p_W2_l;
    if (!p_h) {
        cudaGetSymbolAddress((void **)&p_h,    g_h);
        cudaGetSymbolAddress((void **)&p_hs,   g_hs);
        cudaGetSymbolAddress((void **)&p_dinv, g_dinv);
        cudaGetSymbolAddress((void **)&p_pool, g_pool);
        cudaGetSymbolAddress((void **)&p_deg,  g_deg);
        cudaGetSymbolAddress((void **)&p_We_h, g_Wemb_h);
        cudaGetSymbolAddress((void **)&p_We_l, g_Wemb_l);
        cudaGetSymbolAddress((void **)&p_W1_h, g_Wc1_h);
        cudaGetSymbolAddress((void **)&p_W1_l, g_Wc1_l);
        cudaGetSymbolAddress((void **)&p_W2_h, g_Wc2_h);
        cudaGetSymbolAddress((void **)&p_W2_l, g_Wc2_l);
        cudaFuncSetAttribute(hmma_gemm,
                             cudaFuncAttributeMaxDynamicSharedMemorySize, MMA_SMEM);
    }

    const int mma_grid  = (N + 127) / 128;
    const int agg_grid  = (N * 32 + 255) / 256;

    // launch order: hmma_gemm (GEMM1) at index 3 (profiled slot)
    k_prepW<<<(K_IN * HID + 255) / 256, 256>>>(W_emb, p_We_h, p_We_l, K_IN); // 0
    k_zero_deg<<<(N + 255) / 256, 256>>>(p_deg, N);                          // 1
    k_deg <<<(E + 255) / 256, 256>>>(ei, E);                                 // 2
    hmma_gemm<<<mma_grid, 256, MMA_SMEM>>>(x, p_We_h, p_We_l, b_emb, nullptr,
                                           p_h, N, K_IN);                    // 3
    k_dinv<<<(N + 255) / 256, 256>>>(N);
    k_prepW<<<(HID * HID + 255) / 256, 256>>>(W_c1, p_W1_h, p_W1_l, HID);
    k_prepW<<<(HID * HID + 255) / 256, 256>>>(W_c2, p_W2_h, p_W2_l, HID);

    // CSR build
    k_scan1<<<NSCANB, 256>>>(N);
    k_scan2<<<1, 256>>>();
    k_scan3<<<(N + 255) / 256, 256>>>(N, E);
    k_fill <<<(E + 255) / 256, 256>>>(ei, E);

    // conv1
    hmma_gemm<<<mma_grid, 256, MMA_SMEM>>>(p_h, p_W1_h, p_W1_l, nullptr, p_dinv,
                                           p_hs, N, HID);
    k_agg<<<agg_grid, 256>>>(p_hs, b_c1, p_h, 1, N);

    // conv2
    hmma_gemm<<<mma_grid, 256, MMA_SMEM>>>(p_h, p_W2_h, p_W2_l, nullptr, p_dinv,
                                           p_hs, N, HID);
    k_agg<<<agg_grid, 256>>>(p_hs, b_c2, p_h, 0, N);

    // pool + head
    k_zero4<<<(NGRAPH * (HID + 1) / 4 + 255) / 256, 256>>>((float4 *)p_pool,
                                                           NGRAPH * (HID + 1) / 4);
    k_pool<<<(N + 7) / 8, 256>>>(batch, N, p_h, p_pool);
    k_head<<<NGRAPH, HID>>>(p_pool, W_l1, b_l1, W_l2, b_l2, out);
}

// round 11
// speedup vs baseline: 2.0823x; 1.0315x over previous
#include <cuda_runtime.h>
#include <cuda_bf16.h>
#include <cstdint>

#define NNODES  50000
#define MAXE    800000
#define HID     128
#define INDIM   768
#define NGRAPH  128
#define NCLS    3
#define NSCANB  196             // ceil(50000/256)

// GEMM tiling: BM=128, BN=128, BK=32
#define BK      32
#define ASTRIDE 80
#define ABUF    10240           // 128 * 80
#define BBUF    10240
#define BUFSZ   40960           // 2*ABUF + 2*BBUF
#define MMA_SMEM (2 * BUFSZ)    // 81920

// ---------------- scratch -------------------------------------------------
__device__ float g_h   [NNODES * HID];
__device__ float g_hs  [NNODES * HID];
__device__ float g_dinv[NNODES];
__device__ int   g_deg [NNODES];
__device__ int   g_start[NNODES + 1];
__device__ int   g_cursor[NNODES];
__device__ int   g_bsum[NSCANB];
__device__ int   g_csr [MAXE];
__device__ float g_pool[NGRAPH * HID + NGRAPH];
__device__ __nv_bfloat16 g_Wemb_h[HID * INDIM], g_Wemb_l[HID * INDIM];
__device__ __nv_bfloat16 g_Wc1_h [HID * HID],   g_Wc1_l [HID * HID];
__device__ __nv_bfloat16 g_Wc2_h [HID * HID],   g_Wc2_l [HID * HID];

// ---------------- helpers -------------------------------------------------
__device__ __forceinline__ uint32_t s2u(const void *p) {
    uint32_t a;
    asm("{ .reg .u64 t; cvta.to.shared.u64 t, %1; cvt.u32.u64 %0, t; }"
        : "=r"(a) : "l"(p));
    return a;
}
__device__ __forceinline__ void red4(float *p, float4 v) {
    asm volatile("red.global.add.v4.f32 [%0], {%1, %2, %3, %4};"
                 :: "l"(p), "f"(v.x), "f"(v.y), "f"(v.z), "f"(v.w) : "memory");
}
__device__ __forceinline__ void ldsm4(uint32_t &r0, uint32_t &r1, uint32_t &r2,
                                      uint32_t &r3, uint32_t addr) {
    asm volatile("ldmatrix.sync.aligned.m8n8.x4.shared.b16 {%0,%1,%2,%3}, [%4];"
                 : "=r"(r0), "=r"(r1), "=r"(r2), "=r"(r3) : "r"(addr));
}
__device__ __forceinline__ void mma16816(float *c, const uint32_t *a,
                                         const uint32_t *b) {
    asm volatile(
        "mma.sync.aligned.m16n8k16.row.col.f32.bf16.bf16.f32 "
        "{%0,%1,%2,%3}, {%4,%5,%6,%7}, {%8,%9}, {%0,%1,%2,%3};"
        : "+f"(c[0]), "+f"(c[1]), "+f"(c[2]), "+f"(c[3])
        : "r"(a[0]), "r"(a[1]), "r"(a[2]), "r"(a[3]), "r"(b[0]), "r"(b[1]));
}
__device__ __forceinline__ void cpa16(uint32_t s, const void *g) {
    asm volatile("cp.async.cg.shared.global [%0], [%1], 16;" :: "r"(s), "l"(g));
}
__device__ __forceinline__ void cvt8(const float4 &v0, const float4 &v1,
                                     uint4 &hv, uint4 &lv) {
    __nv_bfloat162 h0 = __floats2bfloat162_rn(v0.x, v0.y);
    __nv_bfloat162 h1 = __floats2bfloat162_rn(v0.z, v0.w);
    __nv_bfloat162 h2 = __floats2bfloat162_rn(v1.x, v1.y);
    __nv_bfloat162 h3 = __floats2bfloat162_rn(v1.z, v1.w);
    __nv_bfloat162 l0 = __floats2bfloat162_rn(v0.x - __bfloat162float(h0.x),
                                              v0.y - __bfloat162float(h0.y));
    __nv_bfloat162 l1 = __floats2bfloat162_rn(v0.z - __bfloat162float(h1.x),
                                              v0.w - __bfloat162float(h1.y));
    __nv_bfloat162 l2 = __floats2bfloat162_rn(v1.x - __bfloat162float(h2.x),
                                              v1.y - __bfloat162float(h2.y));
    __nv_bfloat162 l3 = __floats2bfloat162_rn(v1.z - __bfloat162float(h3.x),
                                              v1.w - __bfloat162float(h3.y));
    hv = make_uint4(*(uint32_t *)&h0, *(uint32_t *)&h1,
                    *(uint32_t *)&h2, *(uint32_t *)&h3);
    lv = make_uint4(*(uint32_t *)&l0, *(uint32_t *)&l1,
                    *(uint32_t *)&l2, *(uint32_t *)&l3);
}

// ---------------- misc small kernels --------------------------------------
__global__ void k_zero4(float4 *__restrict__ p, int n4) {
    int i = blockIdx.x * blockDim.x + threadIdx.x;
    if (i < n4) p[i] = make_float4(0.f, 0.f, 0.f, 0.f);
}
__global__ void k_zero_deg(int *__restrict__ p, int n) {
    int i = blockIdx.x * blockDim.x + threadIdx.x;
    if (i < n) p[i] = 0;
}
__global__ void k_deg(const int *__restrict__ ei, int E) {
    int i = blockIdx.x * blockDim.x + threadIdx.x;
    if (i < E) atomicAdd(&g_deg[ei[E + i]], 1);
}
__global__ void k_dinv(int N) {
    int i = blockIdx.x * blockDim.x + threadIdx.x;
    if (i < N) g_dinv[i] = rsqrtf((float)g_deg[i] + 1.0f);
}

// ---------------- CSR build: scan + fill ----------------------------------
__global__ void k_scan1(int N) {
    __shared__ int sh[256];
    int i = blockIdx.x * 256 + threadIdx.x;
    int v = (i < N) ? g_deg[i] : 0;
    sh[threadIdx.x] = v;
    __syncthreads();
    int x = v;
#pragma unroll
    for (int o = 1; o < 256; o <<= 1) {
        int y = (threadIdx.x >= o) ? sh[threadIdx.x - o] : 0;
        __syncthreads();
        x += y; sh[threadIdx.x] = x;
        __syncthreads();
    }
    if (i < N) g_start[i] = x - v;
    if (threadIdx.x == 255) g_bsum[blockIdx.x] = x;
}
__global__ void k_scan2() {
    __shared__ int sh[256];
    int v = (threadIdx.x < NSCANB) ? g_bsum[threadIdx.x] : 0;
    sh[threadIdx.x] = v;
    __syncthreads();
    int x = v;
#pragma unroll
    for (int o = 1; o < 256; o <<= 1) {
        int y = (threadIdx.x >= o) ? sh[threadIdx.x - o] : 0;
        __syncthreads();
        x += y; sh[threadIdx.x] = x;
        __syncthreads();
    }
    if (threadIdx.x < NSCANB) g_bsum[threadIdx.x] = x - v;
}
__global__ void k_scan3(int N, int E) {
    int i = blockIdx.x * 256 + threadIdx.x;
    if (i < N) {
        int s = g_start[i] + g_bsum[i >> 8];
        g_start[i] = s;
        g_cursor[i] = s;
    }
    if (i == 0) g_start[N] = E;
}
__global__ void k_fill(const int *__restrict__ ei, int E) {
    int i = blockIdx.x * blockDim.x + threadIdx.x;
    if (i >= E) return;
    int d = ei[E + i];
    int pos = atomicAdd(&g_cursor[d], 1);
    g_csr[pos] = ei[i];
}

// ---------------- W prep --------------------------------------------------
__global__ void k_prepW(const float *__restrict__ W, __nv_bfloat16 *__restrict__ Bh,
                        __nv_bfloat16 *__restrict__ Bl, int K) {
    int i = blockIdx.x * blockDim.x + threadIdx.x;
    if (i >= K * HID) return;
    int k = i / HID, n = i % HID;
    float v = W[i];
    __nv_bfloat16 h = __float2bfloat16(v);
    __nv_bfloat16 l = __float2bfloat16(v - __bfloat162float(h));
    Bh[(size_t)n * K + k] = h;
    Bl[(size_t)n * K + k] = l;
}

// ---------------- HMMA GEMM (BM=128, double-buffered, cp.async) ------------
// warps: 4m x 2n; warp tile m32 n64. Term-major MMA order (chain distance 4).
__global__ void __launch_bounds__(256, 2)
hmma_gemm(const float *__restrict__ A,
          const __nv_bfloat16 *__restrict__ Bhg,
          const __nv_bfloat16 *__restrict__ Blg,
          const float *__restrict__ bias, const float *__restrict__ dinv,
          float *__restrict__ C, int M, int K)
{
    extern __shared__ __align__(1024) char smem[];
    const uint32_t sb = s2u(smem);
    const int tid = threadIdx.x;
    const int wid = tid >> 5, lane = tid & 31;
    const int warp_m = wid & 3, warp_n = wid >> 2;
    const int bm0 = blockIdx.x * 128;

    const int alr = tid >> 1, alq = tid & 1;
    int arow = bm0 + alr; if (arow >= M) arow = M - 1;
    const float *Ar = A + (size_t)arow * K + alq * 16;
    const uint32_t a_sts = (uint32_t)(alr * ASTRIDE + alq * 32);

    const int bln = tid >> 1, blu = tid & 1;
    const __nv_bfloat16 *Bhr = Bhg + (size_t)bln * K + blu * 16;
    const __nv_bfloat16 *Blr = Blg + (size_t)bln * K + blu * 16;
    const uint32_t b_sts = (uint32_t)(bln * ASTRIDE + blu * 32);

    const int sub = lane >> 3, lr8 = lane & 7;
    uint32_t a_off[2], b_off[4];
#pragma unroll
    for (int mi = 0; mi < 2; ++mi) {
        int row = warp_m * 32 + mi * 16 + ((sub & 1) << 3) + lr8;
        a_off[mi] = (uint32_t)(row * ASTRIDE + ((sub >> 1) << 4));
    }
#pragma unroll
    for (int np = 0; np < 4; ++np) {
        int nr = warp_n * 64 + np * 16 + ((sub >> 1) << 3) + lr8;
        b_off[np] = (uint32_t)(nr * ASTRIDE + ((sub & 1) << 4));
    }

    float acc[2][8][4];
#pragma unroll
    for (int mi = 0; mi < 2; ++mi)
#pragma unroll
        for (int ni = 0; ni < 8; ++ni)
#pragma unroll
            for (int q = 0; q < 4; ++q) acc[mi][ni][q] = 0.f;

    const int NC = K / BK;
    float4 va0, va1, va2, va3;

    // ---- prologue ----
    va0 = *(const float4 *)(Ar);
    va1 = *(const float4 *)(Ar + 4);
    va2 = *(const float4 *)(Ar + 8);
    va3 = *(const float4 *)(Ar + 12);
    {
        uint32_t s0 = sb + 2 * ABUF + b_sts;
        cpa16(s0,             Bhr);
        cpa16(s0 + 16,        Bhr + 8);
        cpa16(s0 + BBUF,      Blr);
        cpa16(s0 + BBUF + 16, Blr + 8);
        asm volatile("cp.async.commit_group;" ::: "memory");
    }
    {
        uint4 hv, lv;
        cvt8(va0, va1, hv, lv);
        *(uint4 *)(smem + a_sts)        = hv;
        *(uint4 *)(smem + ABUF + a_sts) = lv;
        cvt8(va2, va3, hv, lv);
        *(uint4 *)(smem + a_sts + 16)        = hv;
        *(uint4 *)(smem + ABUF + a_sts + 16) = lv;
    }
    asm volatile("cp.async.wait_group 0;" ::: "memory");
    __syncthreads();

    for (int c = 0; c < NC; ++c) {
        const uint32_t bo = (c & 1) ? (uint32_t)BUFSZ : 0u;
        const uint32_t bn = (c & 1) ? 0u : (uint32_t)BUFSZ;
        const bool more = (c + 1 < NC);
        if (more) {
            const int k1 = (c + 1) * BK;
            va0 = *(const float4 *)(Ar + k1);
            va1 = *(const float4 *)(Ar + k1 + 4);
            va2 = *(const float4 *)(Ar + k1 + 8);
            va3 = *(const float4 *)(Ar + k1 + 12);
            uint32_t s0 = sb + bn + 2 * ABUF + b_sts;
            cpa16(s0,             Bhr + k1);
            cpa16(s0 + 16,        Bhr + k1 + 8);
            cpa16(s0 + BBUF,      Blr + k1);
            cpa16(s0 + BBUF + 16, Blr + k1 + 8);
            asm volatile("cp.async.commit_group;" ::: "memory");
        }

#pragma unroll
        for (int ks = 0; ks < 2; ++ks) {
            uint32_t ahi[2][4], alo[2][4];
#pragma unroll
            for (int mi = 0; mi < 2; ++mi) {
                uint32_t ad = sb + bo + a_off[mi] + ks * 32;
                ldsm4(ahi[mi][0], ahi[mi][1], ahi[mi][2], ahi[mi][3], ad);
                ldsm4(alo[mi][0], alo[mi][1], alo[mi][2], alo[mi][3], ad + ABUF);
            }
#pragma unroll
            for (int np = 0; np < 4; ++np) {
                uint32_t bhi[2][2], blo[2][2];
                uint32_t bd = sb + bo + 2 * ABUF + b_off[np] + ks * 32;
                ldsm4(bhi[0][0], bhi[0][1], bhi[1][0], bhi[1][1], bd);
                ldsm4(blo[0][0], blo[0][1], blo[1][0], blo[1][1], bd + BBUF);
                // term-major: 4 independent accs per term -> chain distance 4
#pragma unroll
                for (int mi = 0; mi < 2; ++mi)
#pragma unroll
                    for (int h = 0; h < 2; ++h)
                        mma16816(acc[mi][np * 2 + h], ahi[mi], bhi[h]);
#pragma unroll
                for (int mi = 0; mi < 2; ++mi)
#pragma unroll
                    for (int h = 0; h < 2; ++h)
                        mma16816(acc[mi][np * 2 + h], ahi[mi], blo[h]);
#pragma unroll
                for (int mi = 0; mi < 2; ++mi)
#pragma unroll
                    for (int h = 0; h < 2; ++h)
                        mma16816(acc[mi][np * 2 + h], alo[mi], bhi[h]);
            }
        }

        if (more) {
            uint4 hv, lv;
            cvt8(va0, va1, hv, lv);
            *(uint4 *)(smem + bn + a_sts)        = hv;
            *(uint4 *)(smem + bn + ABUF + a_sts) = lv;
            cvt8(va2, va3, hv, lv);
            *(uint4 *)(smem + bn + a_sts + 16)        = hv;
            *(uint4 *)(smem + bn + ABUF + a_sts + 16) = lv;
            asm volatile("cp.async.wait_group 0;" ::: "memory");
        }
        __syncthreads();
    }

    // ---- epilogue ----
    const int gid = lane >> 2, qid = lane & 3;
#pragma unroll
    for (int mi = 0; mi < 2; ++mi) {
        int row0 = bm0 + warp_m * 32 + mi * 16 + gid;
        int row1 = row0 + 8;
        float s0 = 1.f, s1 = 1.f;
        if (dinv) {
            if (row0 < M) s0 = dinv[row0];
            if (row1 < M) s1 = dinv[row1];
        }
#pragma unroll
        for (int ni = 0; ni < 8; ++ni) {
            int col = warp_n * 64 + ni * 8 + qid * 2;
            float b0 = 0.f, b1 = 0.f;
            if (bias) { b0 = bias[col]; b1 = bias[col + 1]; }
            if (row0 < M) {
                float2 o = make_float2(fmaf(acc[mi][ni][0], s0, b0),
                                       fmaf(acc[mi][ni][1], s0, b1));
                *(float2 *)&C[(size_t)row0 * HID + col] = o;
            }
            if (row1 < M) {
                float2 o = make_float2(fmaf(acc[mi][ni][2], s1, b0),
                                       fmaf(acc[mi][ni][3], s1, b1));
                *(float2 *)&C[(size_t)row1 * HID + col] = o;
            }
        }
    }
}

// ---------------- CSR aggregate: warp per node -----------------------------
__global__ void __launch_bounds__(256)
k_agg(const float *__restrict__ hs, const float *__restrict__ bias,
      float *__restrict__ outp, int relu, int N)
{
    int node = (blockIdx.x * blockDim.x + threadIdx.x) >> 5;
    if (node >= N) return;
    int lane = threadIdx.x & 31;
    int c = lane * 4;

    int e0 = g_start[node], e1 = g_start[node + 1];
    float4 acc = *(const float4 *)&hs[(size_t)node * HID + c];

    int e = e0;
    for (; e + 4 <= e1; e += 4) {
        int i0 = g_csr[e], i1 = g_csr[e + 1], i2 = g_csr[e + 2], i3 = g_csr[e + 3];
        float4 v0 = *(const float4 *)&hs[(size_t)i0 * HID + c];
        float4 v1 = *(const float4 *)&hs[(size_t)i1 * HID + c];
        float4 v2 = *(const float4 *)&hs[(size_t)i2 * HID + c];
        float4 v3 = *(const float4 *)&hs[(size_t)i3 * HID + c];
        acc.x += v0.x + v1.x + v2.x + v3.x;
        acc.y += v0.y + v1.y + v2.y + v3.y;
        acc.z += v0.z + v1.z + v2.z + v3.z;
        acc.w += v0.w + v1.w + v2.w + v3.w;
    }
    for (; e < e1; ++e) {
        int i0 = g_csr[e];
        float4 v0 = *(const float4 *)&hs[(size_t)i0 * HID + c];
        acc.x += v0.x; acc.y += v0.y; acc.z += v0.z; acc.w += v0.w;
    }

    float dv = g_dinv[node];
    float4 b = *(const float4 *)&bias[c];
    float4 o;
    o.x = fmaf(dv, acc.x, b.x);
    o.y = fmaf(dv, acc.y, b.y);
    o.z = fmaf(dv, acc.z, b.z);
    o.w = fmaf(dv, acc.w, b.w);
    if (relu) {
        o.x = fmaxf(o.x, 0.f); o.y = fmaxf(o.y, 0.f);
        o.z = fmaxf(o.z, 0.f); o.w = fmaxf(o.w, 0.f);
    }
    *(float4 *)&outp[(size_t)node * HID + c] = o;
}

// ---------------- pooling / head ------------------------------------------
__global__ void k_pool(const int *__restrict__ batch, int N,
                       const float *__restrict__ h, float *__restrict__ pool)
{
    int w = (blockIdx.x * blockDim.x + threadIdx.x) >> 5;
    if (w >= N) return;
    int lane = threadIdx.x & 31;
    int b = batch[w];
    float4 v = *(const float4 *)&h[(size_t)w * HID + lane * 4];
    red4(&pool[(size_t)b * HID + lane * 4], v);
    if (lane == 0) atomicAdd(&pool[NGRAPH * HID + b], 1.0f);
}
__global__ void k_head(const float *__restrict__ pool,
                       const float *__restrict__ W1, const float *__restrict__ b1,
                       const float *__restrict__ W2, const float *__restrict__ b2,
                       float *__restrict__ out)
{
    __shared__ float gv[HID];
    __shared__ float hid[HID];
    int g = blockIdx.x, t = threadIdx.x;
    float cnt = fmaxf(pool[NGRAPH * HID + g], 1.0f);
    gv[t] = pool[(size_t)g * HID + t] / cnt;
    __syncthreads();
    float acc = b1[t];
#pragma unroll 8
    for (int c = 0; c < HID; ++c) acc = fmaf(gv[c], W1[c * HID + t], acc);
    hid[t] = fmaxf(acc, 0.f);
    __syncthreads();
    if (t < NCLS) {
        float o = b2[t];
#pragma unroll 8
        for (int hh = 0; hh < HID; ++hh) o = fmaf(hid[hh], W2[hh * NCLS + t], o);
        out[g * NCLS + t] = o;
    }
}

// ---------------- launcher -------------------------------------------------
extern "C" void kernel_launch(void *const *d_in, const int *in_sizes, int n_in,
                              void *d_out, int out_size)
{
    const float *x     = (const float *)d_in[0];
    const int   *ei    = (const int *)d_in[1];
    const int   *batch = (const int *)d_in[2];
    const float *W_emb = (const float *)d_in[3], *b_emb = (const float *)d_in[4];
    const float *W_c1  = (const float *)d_in[5], *b_c1  = (const float *)d_in[6];
    const float *W_c2  = (const float *)d_in[7], *b_c2  = (const float *)d_in[8];
    const float *W_l1  = (const float *)d_in[9], *b_l1  = (const float *)d_in[10];
    const float *W_l2  = (const float *)d_in[11], *b_l2 = (const float *)d_in[12];
    float *out = (float *)d_out;

    const int E = in_sizes[1] / 2;
    const int N = in_sizes[2];
    const int K_IN = in_sizes[0] / N;

    static float *p_h = nullptr, *p_hs = nullptr, *p_dinv = nullptr,
                 *p_pool = nullptr;
    static int *p_deg = nullptr;
    static __nv_bfloat16 *p_We_h, *p_We_l, *p_W1_h, *p_W1_l, *p_W2_h, *p_W2_l;
    if (!p_h) {
        cudaGetSymbolAddress((void **)&p_h,    g_h);
        cudaGetSymbolAddress((void **)&p_hs,   g_hs);
        cudaGetSymbolAddress((void **)&p_dinv, g_dinv);
        cudaGetSymbolAddress((void **)&p_pool, g_pool);
        cudaGetSymbolAddress((void **)&p_deg,  g_deg);
        cudaGetSymbolAddress((void **)&p_We_h, g_Wemb_h);
        cudaGetSymbolAddress((void **)&p_We_l, g_Wemb_l);
        cudaGetSymbolAddress((void **)&p_W1_h, g_Wc1_h);
        cudaGetSymbolAddress((void **)&p_W1_l, g_Wc1_l);
        cudaGetSymbolAddress((void **)&p_W2_h, g_Wc2_h);
        cudaGetSymbolAddress((void **)&p_W2_l, g_Wc2_l);
        cudaFuncSetAttribute(hmma_gemm,
                             cudaFuncAttributeMaxDynamicSharedMemorySize, MMA_SMEM);
    }

    const int mma_grid  = (N + 127) / 128;
    const int agg_grid  = (N * 32 + 255) / 256;

    // launch order: hmma_gemm (GEMM1) at index 3 (profiled slot)
    k_prepW<<<(K_IN * HID + 255) / 256, 256>>>(W_emb, p_We_h, p_We_l, K_IN); // 0
    k_zero_deg<<<(N + 255) / 256, 256>>>(p_deg, N);                          // 1
    k_deg <<<(E + 255) / 256, 256>>>(ei, E);                                 // 2
    hmma_gemm<<<mma_grid, 256, MMA_SMEM>>>(x, p_We_h, p_We_l, b_emb, nullptr,
                                           p_h, N, K_IN);                    // 3
    k_dinv<<<(N + 255) / 256, 256>>>(N);
    k_prepW<<<(HID * HID + 255) / 256, 256>>>(W_c1, p_W1_h, p_W1_l, HID);
    k_prepW<<<(HID * HID + 255) / 256, 256>>>(W_c2, p_W2_h, p_W2_l, HID);

    // CSR build
    k_scan1<<<NSCANB, 256>>>(N);
    k_scan2<<<1, 256>>>();
    k_scan3<<<(N + 255) / 256, 256>>>(N, E);
    k_fill <<<(E + 255) / 256, 256>>>(ei, E);

    // conv1
    hmma_gemm<<<mma_grid, 256, MMA_SMEM>>>(p_h, p_W1_h, p_W1_l, nullptr, p_dinv,
                                           p_hs, N, HID);
    k_agg<<<agg_grid, 256>>>(p_hs, b_c1, p_h, 1, N);

    // conv2
    hmma_gemm<<<mma_grid, 256, MMA_SMEM>>>(p_h, p_W2_h, p_W2_l, nullptr, p_dinv,
                                           p_hs, N, HID);
    k_agg<<<agg_grid, 256>>>(p_hs, b_c2, p_h, 0, N);

    // pool + head
    k_zero4<<<(NGRAPH * (HID + 1) / 4 + 255) / 256, 256>>>((float4 *)p_pool,
                                                           NGRAPH * (HID + 1) / 4);
    k_pool<<<(N + 7) / 8, 256>>>(batch, N, p_h, p_pool);
    k_head<<<NGRAPH, HID>>>(p_pool, W_l1, b_l1, W_l2, b_l2, out);
}

// round 12
// speedup vs baseline: 2.2144x; 1.0634x over previous
#include <cuda_runtime.h>
#include <cuda_bf16.h>
#include <cstdint>

#define NNODES  50000
#define MAXE    800000
#define HID     128
#define INDIM   768
#define NGRAPH  128
#define NCLS    3
#define NSCANB  196             // ceil(50000/256)

// GEMM tiling: BM=128, BN=128, BK=32
#define BK      32
#define ASTRIDE 80
#define ABUF    10240           // 128 * 80
#define BBUF    10240
#define BUFSZ   40960           // 2*ABUF + 2*BBUF
#define MMA_SMEM (2 * BUFSZ)    // 81920

// ---------------- scratch -------------------------------------------------
__device__ float g_h   [NNODES * HID];
__device__ float g_hs  [NNODES * HID];
__device__ float g_dinv[NNODES];
__device__ int   g_deg [NNODES];
__device__ int   g_start[NNODES + 1];
__device__ int   g_cursor[NNODES];
__device__ int   g_bsum[NSCANB];
__device__ int   g_csr [MAXE];
__device__ float g_pool[NGRAPH * HID + NGRAPH];
__device__ __nv_bfloat16 g_Wemb_h[HID * INDIM], g_Wemb_l[HID * INDIM];
__device__ __nv_bfloat16 g_Wc1_h [HID * HID],   g_Wc1_l [HID * HID];
__device__ __nv_bfloat16 g_Wc2_h [HID * HID],   g_Wc2_l [HID * HID];

// ---------------- helpers -------------------------------------------------
__device__ __forceinline__ uint32_t s2u(const void *p) {
    uint32_t a;
    asm("{ .reg .u64 t; cvta.to.shared.u64 t, %1; cvt.u32.u64 %0, t; }"
        : "=r"(a) : "l"(p));
    return a;
}
__device__ __forceinline__ void red4(float *p, float4 v) {
    asm volatile("red.global.add.v4.f32 [%0], {%1, %2, %3, %4};"
                 :: "l"(p), "f"(v.x), "f"(v.y), "f"(v.z), "f"(v.w) : "memory");
}
__device__ __forceinline__ void ldsm4(uint32_t &r0, uint32_t &r1, uint32_t &r2,
                                      uint32_t &r3, uint32_t addr) {
    asm volatile("ldmatrix.sync.aligned.m8n8.x4.shared.b16 {%0,%1,%2,%3}, [%4];"
                 : "=r"(r0), "=r"(r1), "=r"(r2), "=r"(r3) : "r"(addr));
}
__device__ __forceinline__ void mma16816(float *c, const uint32_t *a,
                                         const uint32_t *b) {
    asm volatile(
        "mma.sync.aligned.m16n8k16.row.col.f32.bf16.bf16.f32 "
        "{%0,%1,%2,%3}, {%4,%5,%6,%7}, {%8,%9}, {%0,%1,%2,%3};"
        : "+f"(c[0]), "+f"(c[1]), "+f"(c[2]), "+f"(c[3])
        : "r"(a[0]), "r"(a[1]), "r"(a[2]), "r"(a[3]), "r"(b[0]), "r"(b[1]));
}
__device__ __forceinline__ void cpa16(uint32_t s, const void *g) {
    asm volatile("cp.async.cg.shared.global [%0], [%1], 16;" :: "r"(s), "l"(g));
}
__device__ __forceinline__ void cvt8(const float4 &v0, const float4 &v1,
                                     uint4 &hv, uint4 &lv) {
    __nv_bfloat162 h0 = __floats2bfloat162_rn(v0.x, v0.y);
    __nv_bfloat162 h1 = __floats2bfloat162_rn(v0.z, v0.w);
    __nv_bfloat162 h2 = __floats2bfloat162_rn(v1.x, v1.y);
    __nv_bfloat162 h3 = __floats2bfloat162_rn(v1.z, v1.w);
    __nv_bfloat162 l0 = __floats2bfloat162_rn(v0.x - __bfloat162float(h0.x),
                                              v0.y - __bfloat162float(h0.y));
    __nv_bfloat162 l1 = __floats2bfloat162_rn(v0.z - __bfloat162float(h1.x),
                                              v0.w - __bfloat162float(h1.y));
    __nv_bfloat162 l2 = __floats2bfloat162_rn(v1.x - __bfloat162float(h2.x),
                                              v1.y - __bfloat162float(h2.y));
    __nv_bfloat162 l3 = __floats2bfloat162_rn(v1.z - __bfloat162float(h3.x),
                                              v1.w - __bfloat162float(h3.y));
    hv = make_uint4(*(uint32_t *)&h0, *(uint32_t *)&h1,
                    *(uint32_t *)&h2, *(uint32_t *)&h3);
    lv = make_uint4(*(uint32_t *)&l0, *(uint32_t *)&l1,
                    *(uint32_t *)&l2, *(uint32_t *)&l3);
}

// ---------------- misc small kernels --------------------------------------
__global__ void k_zero4(float4 *__restrict__ p, int n4) {
    int i = blockIdx.x * blockDim.x + threadIdx.x;
    if (i < n4) p[i] = make_float4(0.f, 0.f, 0.f, 0.f);
}
__global__ void k_zero_deg(int *__restrict__ p, int n) {
    int i = blockIdx.x * blockDim.x + threadIdx.x;
    if (i < n) p[i] = 0;
}
__global__ void k_deg(const int *__restrict__ ei, int E) {
    int i = blockIdx.x * blockDim.x + threadIdx.x;
    if (i < E) atomicAdd(&g_deg[ei[E + i]], 1);
}
__global__ void k_dinv(int N) {
    int i = blockIdx.x * blockDim.x + threadIdx.x;
    if (i < N) g_dinv[i] = rsqrtf((float)g_deg[i] + 1.0f);
}

// ---------------- CSR build: scan + fill ----------------------------------
__global__ void k_scan1(int N) {
    __shared__ int sh[256];
    int i = blockIdx.x * 256 + threadIdx.x;
    int v = (i < N) ? g_deg[i] : 0;
    sh[threadIdx.x] = v;
    __syncthreads();
    int x = v;
#pragma unroll
    for (int o = 1; o < 256; o <<= 1) {
        int y = (threadIdx.x >= o) ? sh[threadIdx.x - o] : 0;
        __syncthreads();
        x += y; sh[threadIdx.x] = x;
        __syncthreads();
    }
    if (i < N) g_start[i] = x - v;
    if (threadIdx.x == 255) g_bsum[blockIdx.x] = x;
}
__global__ void k_scan2() {
    __shared__ int sh[256];
    int v = (threadIdx.x < NSCANB) ? g_bsum[threadIdx.x] : 0;
    sh[threadIdx.x] = v;
    __syncthreads();
    int x = v;
#pragma unroll
    for (int o = 1; o < 256; o <<= 1) {
        int y = (threadIdx.x >= o) ? sh[threadIdx.x - o] : 0;
        __syncthreads();
        x += y; sh[threadIdx.x] = x;
        __syncthreads();
    }
    if (threadIdx.x < NSCANB) g_bsum[threadIdx.x] = x - v;
}
__global__ void k_scan3(int N, int E) {
    int i = blockIdx.x * 256 + threadIdx.x;
    if (i < N) {
        int s = g_start[i] + g_bsum[i >> 8];
        g_start[i] = s;
        g_cursor[i] = s;
    }
    if (i == 0) g_start[N] = E;
}
__global__ void k_fill(const int *__restrict__ ei, int E) {
    int i = blockIdx.x * blockDim.x + threadIdx.x;
    if (i >= E) return;
    int d = ei[E + i];
    int pos = atomicAdd(&g_cursor[d], 1);
    g_csr[pos] = ei[i];
}

// ---------------- W prep --------------------------------------------------
__global__ void k_prepW(const float *__restrict__ W, __nv_bfloat16 *__restrict__ Bh,
                        __nv_bfloat16 *__restrict__ Bl, int K) {
    int i = blockIdx.x * blockDim.x + threadIdx.x;
    if (i >= K * HID) return;
    int k = i / HID, n = i % HID;
    float v = W[i];
    __nv_bfloat16 h = __float2bfloat16(v);
    __nv_bfloat16 l = __float2bfloat16(v - __bfloat162float(h));
    Bh[(size_t)n * K + k] = h;
    Bl[(size_t)n * K + k] = l;
}

// ---------------- HMMA GEMM (BM=128, double-buffered, cp.async) ------------
__global__ void __launch_bounds__(256, 2)
hmma_gemm(const float *__restrict__ A,
          const __nv_bfloat16 *__restrict__ Bhg,
          const __nv_bfloat16 *__restrict__ Blg,
          const float *__restrict__ bias, const float *__restrict__ dinv,
          float *__restrict__ C, int M, int K)
{
    extern __shared__ __align__(1024) char smem[];
    const uint32_t sb = s2u(smem);
    const int tid = threadIdx.x;
    const int wid = tid >> 5, lane = tid & 31;
    const int warp_m = wid & 3, warp_n = wid >> 2;
    const int bm0 = blockIdx.x * 128;

    const int alr = tid >> 1, alq = tid & 1;
    int arow = bm0 + alr; if (arow >= M) arow = M - 1;
    const float *Ar = A + (size_t)arow * K + alq * 16;
    const uint32_t a_sts = (uint32_t)(alr * ASTRIDE + alq * 32);

    const int bln = tid >> 1, blu = tid & 1;
    const __nv_bfloat16 *Bhr = Bhg + (size_t)bln * K + blu * 16;
    const __nv_bfloat16 *Blr = Blg + (size_t)bln * K + blu * 16;
    const uint32_t b_sts = (uint32_t)(bln * ASTRIDE + blu * 32);

    const int sub = lane >> 3, lr8 = lane & 7;
    uint32_t a_off[2], b_off[4];
#pragma unroll
    for (int mi = 0; mi < 2; ++mi) {
        int row = warp_m * 32 + mi * 16 + ((sub & 1) << 3) + lr8;
        a_off[mi] = (uint32_t)(row * ASTRIDE + ((sub >> 1) << 4));
    }
#pragma unroll
    for (int np = 0; np < 4; ++np) {
        int nr = warp_n * 64 + np * 16 + ((sub >> 1) << 3) + lr8;
        b_off[np] = (uint32_t)(nr * ASTRIDE + ((sub & 1) << 4));
    }

    float acc[2][8][4];
#pragma unroll
    for (int mi = 0; mi < 2; ++mi)
#pragma unroll
        for (int ni = 0; ni < 8; ++ni)
#pragma unroll
            for (int q = 0; q < 4; ++q) acc[mi][ni][q] = 0.f;

    const int NC = K / BK;
    float4 va0, va1, va2, va3;

    // ---- prologue ----
    va0 = *(const float4 *)(Ar);
    va1 = *(const float4 *)(Ar + 4);
    va2 = *(const float4 *)(Ar + 8);
    va3 = *(const float4 *)(Ar + 12);
    {
        uint32_t s0 = sb + 2 * ABUF + b_sts;
        cpa16(s0,             Bhr);
        cpa16(s0 + 16,        Bhr + 8);
        cpa16(s0 + BBUF,      Blr);
        cpa16(s0 + BBUF + 16, Blr + 8);
        asm volatile("cp.async.commit_group;" ::: "memory");
    }
    {
        uint4 hv, lv;
        cvt8(va0, va1, hv, lv);
        *(uint4 *)(smem + a_sts)        = hv;
        *(uint4 *)(smem + ABUF + a_sts) = lv;
        cvt8(va2, va3, hv, lv);
        *(uint4 *)(smem + a_sts + 16)        = hv;
        *(uint4 *)(smem + ABUF + a_sts + 16) = lv;
    }
    asm volatile("cp.async.wait_group 0;" ::: "memory");
    __syncthreads();

    for (int c = 0; c < NC; ++c) {
        const uint32_t bo = (c & 1) ? (uint32_t)BUFSZ : 0u;
        const uint32_t bn = (c & 1) ? 0u : (uint32_t)BUFSZ;
        const bool more = (c + 1 < NC);
        if (more) {
            const int k1 = (c + 1) * BK;
            va0 = *(const float4 *)(Ar + k1);
            va1 = *(const float4 *)(Ar + k1 + 4);
            va2 = *(const float4 *)(Ar + k1 + 8);
            va3 = *(const float4 *)(Ar + k1 + 12);
            uint32_t s0 = sb + bn + 2 * ABUF + b_sts;
            cpa16(s0,             Bhr + k1);
            cpa16(s0 + 16,        Bhr + k1 + 8);
            cpa16(s0 + BBUF,      Blr + k1);
            cpa16(s0 + BBUF + 16, Blr + k1 + 8);
            asm volatile("cp.async.commit_group;" ::: "memory");
        }

#pragma unroll
        for (int ks = 0; ks < 2; ++ks) {
            uint32_t ahi[2][4], alo[2][4];
#pragma unroll
            for (int mi = 0; mi < 2; ++mi) {
                uint32_t ad = sb + bo + a_off[mi] + ks * 32;
                ldsm4(ahi[mi][0], ahi[mi][1], ahi[mi][2], ahi[mi][3], ad);
                ldsm4(alo[mi][0], alo[mi][1], alo[mi][2], alo[mi][3], ad + ABUF);
            }
#pragma unroll
            for (int np = 0; np < 4; ++np) {
                uint32_t bhi[2][2], blo[2][2];
                uint32_t bd = sb + bo + 2 * ABUF + b_off[np] + ks * 32;
                ldsm4(bhi[0][0], bhi[0][1], bhi[1][0], bhi[1][1], bd);
                ldsm4(blo[0][0], blo[0][1], blo[1][0], blo[1][1], bd + BBUF);
#pragma unroll
                for (int mi = 0; mi < 2; ++mi)
#pragma unroll
                    for (int h = 0; h < 2; ++h)
                        mma16816(acc[mi][np * 2 + h], ahi[mi], bhi[h]);
#pragma unroll
                for (int mi = 0; mi < 2; ++mi)
#pragma unroll
                    for (int h = 0; h < 2; ++h)
                        mma16816(acc[mi][np * 2 + h], ahi[mi], blo[h]);
#pragma unroll
                for (int mi = 0; mi < 2; ++mi)
#pragma unroll
                    for (int h = 0; h < 2; ++h)
                        mma16816(acc[mi][np * 2 + h], alo[mi], bhi[h]);
            }
        }

        if (more) {
            uint4 hv, lv;
            cvt8(va0, va1, hv, lv);
            *(uint4 *)(smem + bn + a_sts)        = hv;
            *(uint4 *)(smem + bn + ABUF + a_sts) = lv;
            cvt8(va2, va3, hv, lv);
            *(uint4 *)(smem + bn + a_sts + 16)        = hv;
            *(uint4 *)(smem + bn + ABUF + a_sts + 16) = lv;
            asm volatile("cp.async.wait_group 0;" ::: "memory");
        }
        __syncthreads();
    }

    // ---- epilogue ----
    const int gid = lane >> 2, qid = lane & 3;
#pragma unroll
    for (int mi = 0; mi < 2; ++mi) {
        int row0 = bm0 + warp_m * 32 + mi * 16 + gid;
        int row1 = row0 + 8;
        float s0 = 1.f, s1 = 1.f;
        if (dinv) {
            if (row0 < M) s0 = dinv[row0];
            if (row1 < M) s1 = dinv[row1];
        }
#pragma unroll
        for (int ni = 0; ni < 8; ++ni) {
            int col = warp_n * 64 + ni * 8 + qid * 2;
            float b0 = 0.f, b1 = 0.f;
            if (bias) { b0 = bias[col]; b1 = bias[col + 1]; }
            if (row0 < M) {
                float2 o = make_float2(fmaf(acc[mi][ni][0], s0, b0),
                                       fmaf(acc[mi][ni][1], s0, b1));
                *(float2 *)&C[(size_t)row0 * HID + col] = o;
            }
            if (row1 < M) {
                float2 o = make_float2(fmaf(acc[mi][ni][2], s1, b0),
                                       fmaf(acc[mi][ni][3], s1, b1));
                *(float2 *)&C[(size_t)row1 * HID + col] = o;
            }
        }
    }
}

// ---------------- CSR aggregate: warp per node -----------------------------
__global__ void __launch_bounds__(256)
k_agg(const float *__restrict__ hs, const float *__restrict__ bias,
      float *__restrict__ outp, int relu, int N)
{
    int node = (blockIdx.x * blockDim.x + threadIdx.x) >> 5;
    if (node >= N) return;
    int lane = threadIdx.x & 31;
    int c = lane * 4;

    int e0 = g_start[node], e1 = g_start[node + 1];
    float4 acc = *(const float4 *)&hs[(size_t)node * HID + c];

    int e = e0;
    for (; e + 4 <= e1; e += 4) {
        int i0 = g_csr[e], i1 = g_csr[e + 1], i2 = g_csr[e + 2], i3 = g_csr[e + 3];
        float4 v0 = *(const float4 *)&hs[(size_t)i0 * HID + c];
        float4 v1 = *(const float4 *)&hs[(size_t)i1 * HID + c];
        float4 v2 = *(const float4 *)&hs[(size_t)i2 * HID + c];
        float4 v3 = *(const float4 *)&hs[(size_t)i3 * HID + c];
        acc.x += v0.x + v1.x + v2.x + v3.x;
        acc.y += v0.y + v1.y + v2.y + v3.y;
        acc.z += v0.z + v1.z + v2.z + v3.z;
        acc.w += v0.w + v1.w + v2.w + v3.w;
    }
    for (; e < e1; ++e) {
        int i0 = g_csr[e];
        float4 v0 = *(const float4 *)&hs[(size_t)i0 * HID + c];
        acc.x += v0.x; acc.y += v0.y; acc.z += v0.z; acc.w += v0.w;
    }

    float dv = g_dinv[node];
    float4 b = *(const float4 *)&bias[c];
    float4 o;
    o.x = fmaf(dv, acc.x, b.x);
    o.y = fmaf(dv, acc.y, b.y);
    o.z = fmaf(dv, acc.z, b.z);
    o.w = fmaf(dv, acc.w, b.w);
    if (relu) {
        o.x = fmaxf(o.x, 0.f); o.y = fmaxf(o.y, 0.f);
        o.z = fmaxf(o.z, 0.f); o.w = fmaxf(o.w, 0.f);
    }
    *(float4 *)&outp[(size_t)node * HID + c] = o;
}

// ---------------- pooling / head ------------------------------------------
__global__ void k_pool(const int *__restrict__ batch, int N,
                       const float *__restrict__ h, float *__restrict__ pool)
{
    int w = (blockIdx.x * blockDim.x + threadIdx.x) >> 5;
    if (w >= N) return;
    int lane = threadIdx.x & 31;
    int b = batch[w];
    float4 v = *(const float4 *)&h[(size_t)w * HID + lane * 4];
    red4(&pool[(size_t)b * HID + lane * 4], v);
    if (lane == 0) atomicAdd(&pool[NGRAPH * HID + b], 1.0f);
}
__global__ void k_head(const float *__restrict__ pool,
                       const float *__restrict__ W1, const float *__restrict__ b1,
                       const float *__restrict__ W2, const float *__restrict__ b2,
                       float *__restrict__ out)
{
    __shared__ float gv[HID];
    __shared__ float hid[HID];
    int g = blockIdx.x, t = threadIdx.x;
    float cnt = fmaxf(pool[NGRAPH * HID + g], 1.0f);
    gv[t] = pool[(size_t)g * HID + t] / cnt;
    __syncthreads();
    float acc = b1[t];
#pragma unroll 8
    for (int c = 0; c < HID; ++c) acc = fmaf(gv[c], W1[c * HID + t], acc);
    hid[t] = fmaxf(acc, 0.f);
    __syncthreads();
    if (t < NCLS) {
        float o = b2[t];
#pragma unroll 8
        for (int hh = 0; hh < HID; ++hh) o = fmaf(hid[hh], W2[hh * NCLS + t], o);
        out[g * NCLS + t] = o;
    }
}

// ---------------- launcher -------------------------------------------------
extern "C" void kernel_launch(void *const *d_in, const int *in_sizes, int n_in,
                              void *d_out, int out_size)
{
    const float *x     = (const float *)d_in[0];
    const int   *ei    = (const int *)d_in[1];
    const int   *batch = (const int *)d_in[2];
    const float *W_emb = (const float *)d_in[3], *b_emb = (const float *)d_in[4];
    const float *W_c1  = (const float *)d_in[5], *b_c1  = (const float *)d_in[6];
    const float *W_c2  = (const float *)d_in[7], *b_c2  = (const float *)d_in[8];
    const float *W_l1  = (const float *)d_in[9], *b_l1  = (const float *)d_in[10];
    const float *W_l2  = (const float *)d_in[11], *b_l2 = (const float *)d_in[12];
    float *out = (float *)d_out;

    const int E = in_sizes[1] / 2;
    const int N = in_sizes[2];
    const int K_IN = in_sizes[0] / N;

    static float *p_h = nullptr, *p_hs = nullptr, *p_dinv = nullptr,
                 *p_pool = nullptr;
    static int *p_deg = nullptr;
    static __nv_bfloat16 *p_We_h, *p_We_l, *p_W1_h, *p_W1_l, *p_W2_h, *p_W2_l;
    static cudaStream_t s2 = nullptr;
    static cudaEvent_t evFork = nullptr, evJoin = nullptr;
    if (!p_h) {
        cudaGetSymbolAddress((void **)&p_h,    g_h);
        cudaGetSymbolAddress((void **)&p_hs,   g_hs);
        cudaGetSymbolAddress((void **)&p_dinv, g_dinv);
        cudaGetSymbolAddress((void **)&p_pool, g_pool);
        cudaGetSymbolAddress((void **)&p_deg,  g_deg);
        cudaGetSymbolAddress((void **)&p_We_h, g_Wemb_h);
        cudaGetSymbolAddress((void **)&p_We_l, g_Wemb_l);
        cudaGetSymbolAddress((void **)&p_W1_h, g_Wc1_h);
        cudaGetSymbolAddress((void **)&p_W1_l, g_Wc1_l);
        cudaGetSymbolAddress((void **)&p_W2_h, g_Wc2_h);
        cudaGetSymbolAddress((void **)&p_W2_l, g_Wc2_l);
        cudaFuncSetAttribute(hmma_gemm,
                             cudaFuncAttributeMaxDynamicSharedMemorySize, MMA_SMEM);
        cudaStreamCreateWithFlags(&s2, cudaStreamNonBlocking);
        cudaEventCreateWithFlags(&evFork, cudaEventDisableTiming);
        cudaEventCreateWithFlags(&evJoin, cudaEventDisableTiming);
    }

    const int mma_grid  = (N + 127) / 128;
    const int agg_grid  = (N * 32 + 255) / 256;

    // ---- fork: side chain (graph-independent of GEMM1) on s2 ----
    cudaEventRecord(evFork, 0);
    cudaStreamWaitEvent(s2, evFork, 0);

    // side chain: CSR build + dinv + conv weight prep + pool zero
    k_zero_deg<<<(N + 255) / 256, 256, 0, s2>>>(p_deg, N);
    k_deg <<<(E + 255) / 256, 256, 0, s2>>>(ei, E);
    k_dinv<<<(N + 255) / 256, 256, 0, s2>>>(N);
    k_scan1<<<NSCANB, 256, 0, s2>>>(N);
    k_scan2<<<1, 256, 0, s2>>>();
    k_scan3<<<(N + 255) / 256, 256, 0, s2>>>(N, E);
    k_fill <<<(E + 255) / 256, 256, 0, s2>>>(ei, E);
    k_prepW<<<(HID * HID + 255) / 256, 256, 0, s2>>>(W_c1, p_W1_h, p_W1_l, HID);
    k_prepW<<<(HID * HID + 255) / 256, 256, 0, s2>>>(W_c2, p_W2_h, p_W2_l, HID);
    k_zero4<<<(NGRAPH * (HID + 1) / 4 + 255) / 256, 256, 0, s2>>>(
        (float4 *)p_pool, NGRAPH * (HID + 1) / 4);

    // main chain: embedding GEMM
    k_prepW<<<(K_IN * HID + 255) / 256, 256>>>(W_emb, p_We_h, p_We_l, K_IN);
    hmma_gemm<<<mma_grid, 256, MMA_SMEM>>>(x, p_We_h, p_We_l, b_emb, nullptr,
                                           p_h, N, K_IN);

    // ---- join ----
    cudaEventRecord(evJoin, s2);
    cudaStreamWaitEvent(0, evJoin, 0);

    // conv1
    hmma_gemm<<<mma_grid, 256, MMA_SMEM>>>(p_h, p_W1_h, p_W1_l, nullptr, p_dinv,
                                           p_hs, N, HID);
    k_agg<<<agg_grid, 256>>>(p_hs, b_c1, p_h, 1, N);

    // conv2
    hmma_gemm<<<mma_grid, 256, MMA_SMEM>>>(p_h, p_W2_h, p_W2_l, nullptr, p_dinv,
                                           p_hs, N, HID);
    k_agg<<<agg_grid, 256>>>(p_hs, b_c2, p_h, 0, N);

    // pool + head
    k_pool<<<(N + 7) / 8, 256>>>(batch, N, p_h, p_pool);
    k_head<<<NGRAPH, HID>>>(p_pool, W_l1, b_l1, W_l2, b_l2, out);
}

// round 13
// speedup vs baseline: 2.3151x; 1.0455x over previous
#include <cuda_runtime.h>
#include <cuda_bf16.h>
#include <cstdint>

#define NNODES  50000
#define MAXE    800000
#define HID     128
#define INDIM   768
#define NGRAPH  128
#define NCLS    3
#define NSCANB  196             // ceil(50000/256)

// GEMM tiling: BM=128, BN=128, BK=32
#define BK      32
#define ASTRIDE 80
#define ABUF    10240           // 128 * 80
#define BBUF    10240
#define BUFSZ   40960           // 2*ABUF + 2*BBUF
#define MMA_SMEM (2 * BUFSZ)    // 81920

// ---------------- scratch -------------------------------------------------
__device__ float g_h   [NNODES * HID];
__device__ float g_hs  [NNODES * HID];
__device__ float g_dinv[NNODES];
__device__ int   g_deg [NNODES];
__device__ int   g_start[NNODES + 1];
__device__ int   g_cursor[NNODES];
__device__ int   g_bsum[NSCANB];
__device__ int   g_csr [MAXE];
__device__ float g_pool[NGRAPH * HID + NGRAPH];
__device__ __nv_bfloat16 g_Wemb_h[HID * INDIM], g_Wemb_l[HID * INDIM];
__device__ __nv_bfloat16 g_Wc1_h [HID * HID],   g_Wc1_l [HID * HID];
__device__ __nv_bfloat16 g_Wc2_h [HID * HID],   g_Wc2_l [HID * HID];

// ---------------- helpers -------------------------------------------------
__device__ __forceinline__ uint32_t s2u(const void *p) {
    uint32_t a;
    asm("{ .reg .u64 t; cvta.to.shared.u64 t, %1; cvt.u32.u64 %0, t; }"
        : "=r"(a) : "l"(p));
    return a;
}
__device__ __forceinline__ void red4(float *p, float4 v) {
    asm volatile("red.global.add.v4.f32 [%0], {%1, %2, %3, %4};"
                 :: "l"(p), "f"(v.x), "f"(v.y), "f"(v.z), "f"(v.w) : "memory");
}
__device__ __forceinline__ void ldsm4(uint32_t &r0, uint32_t &r1, uint32_t &r2,
                                      uint32_t &r3, uint32_t addr) {
    asm volatile("ldmatrix.sync.aligned.m8n8.x4.shared.b16 {%0,%1,%2,%3}, [%4];"
                 : "=r"(r0), "=r"(r1), "=r"(r2), "=r"(r3) : "r"(addr));
}
__device__ __forceinline__ void mma16816(float *c, const uint32_t *a,
                                         const uint32_t *b) {
    asm volatile(
        "mma.sync.aligned.m16n8k16.row.col.f32.bf16.bf16.f32 "
        "{%0,%1,%2,%3}, {%4,%5,%6,%7}, {%8,%9}, {%0,%1,%2,%3};"
        : "+f"(c[0]), "+f"(c[1]), "+f"(c[2]), "+f"(c[3])
        : "r"(a[0]), "r"(a[1]), "r"(a[2]), "r"(a[3]), "r"(b[0]), "r"(b[1]));
}
__device__ __forceinline__ void cpa16(uint32_t s, const void *g) {
    asm volatile("cp.async.cg.shared.global [%0], [%1], 16;" :: "r"(s), "l"(g));
}
__device__ __forceinline__ void cvt8(const float4 &v0, const float4 &v1,
                                     uint4 &hv, uint4 &lv) {
    __nv_bfloat162 h0 = __floats2bfloat162_rn(v0.x, v0.y);
    __nv_bfloat162 h1 = __floats2bfloat162_rn(v0.z, v0.w);
    __nv_bfloat162 h2 = __floats2bfloat162_rn(v1.x, v1.y);
    __nv_bfloat162 h3 = __floats2bfloat162_rn(v1.z, v1.w);
    __nv_bfloat162 l0 = __floats2bfloat162_rn(v0.x - __bfloat162float(h0.x),
                                              v0.y - __bfloat162float(h0.y));
    __nv_bfloat162 l1 = __floats2bfloat162_rn(v0.z - __bfloat162float(h1.x),
                                              v0.w - __bfloat162float(h1.y));
    __nv_bfloat162 l2 = __floats2bfloat162_rn(v1.x - __bfloat162float(h2.x),
                                              v1.y - __bfloat162float(h2.y));
    __nv_bfloat162 l3 = __floats2bfloat162_rn(v1.z - __bfloat162float(h3.x),
                                              v1.w - __bfloat162float(h3.y));
    hv = make_uint4(*(uint32_t *)&h0, *(uint32_t *)&h1,
                    *(uint32_t *)&h2, *(uint32_t *)&h3);
    lv = make_uint4(*(uint32_t *)&l0, *(uint32_t *)&l1,
                    *(uint32_t *)&l2, *(uint32_t *)&l3);
}

// ---------------- misc small kernels --------------------------------------
__global__ void k_zero4(float4 *__restrict__ p, int n4) {
    int i = blockIdx.x * blockDim.x + threadIdx.x;
    if (i < n4) p[i] = make_float4(0.f, 0.f, 0.f, 0.f);
}
__global__ void k_zero_deg(int *__restrict__ p, int n) {
    int i = blockIdx.x * blockDim.x + threadIdx.x;
    if (i < n) p[i] = 0;
}
__global__ void k_deg(const int *__restrict__ ei, int E) {
    int i = blockIdx.x * blockDim.x + threadIdx.x;
    if (i < E) atomicAdd(&g_deg[ei[E + i]], 1);
}
__global__ void k_dinv(int N) {
    int i = blockIdx.x * blockDim.x + threadIdx.x;
    if (i < N) g_dinv[i] = rsqrtf((float)g_deg[i] + 1.0f);
}

// ---------------- CSR build: scan + fill ----------------------------------
__global__ void k_scan1(int N) {
    __shared__ int sh[256];
    int i = blockIdx.x * 256 + threadIdx.x;
    int v = (i < N) ? g_deg[i] : 0;
    sh[threadIdx.x] = v;
    __syncthreads();
    int x = v;
#pragma unroll
    for (int o = 1; o < 256; o <<= 1) {
        int y = (threadIdx.x >= o) ? sh[threadIdx.x - o] : 0;
        __syncthreads();
        x += y; sh[threadIdx.x] = x;
        __syncthreads();
    }
    if (i < N) g_start[i] = x - v;
    if (threadIdx.x == 255) g_bsum[blockIdx.x] = x;
}
__global__ void k_scan2() {
    __shared__ int sh[256];
    int v = (threadIdx.x < NSCANB) ? g_bsum[threadIdx.x] : 0;
    sh[threadIdx.x] = v;
    __syncthreads();
    int x = v;
#pragma unroll
    for (int o = 1; o < 256; o <<= 1) {
        int y = (threadIdx.x >= o) ? sh[threadIdx.x - o] : 0;
        __syncthreads();
        x += y; sh[threadIdx.x] = x;
        __syncthreads();
    }
    if (threadIdx.x < NSCANB) g_bsum[threadIdx.x] = x - v;
}
__global__ void k_scan3(int N, int E) {
    int i = blockIdx.x * 256 + threadIdx.x;
    if (i < N) {
        int s = g_start[i] + g_bsum[i >> 8];
        g_start[i] = s;
        g_cursor[i] = s;
    }
    if (i == 0) g_start[N] = E;
}
__global__ void k_fill(const int *__restrict__ ei, int E) {
    int i = blockIdx.x * blockDim.x + threadIdx.x;
    if (i >= E) return;
    int d = ei[E + i];
    int pos = atomicAdd(&g_cursor[d], 1);
    g_csr[pos] = ei[i];
}

// ---------------- W prep --------------------------------------------------
__global__ void k_prepW(const float *__restrict__ W, __nv_bfloat16 *__restrict__ Bh,
                        __nv_bfloat16 *__restrict__ Bl, int K) {
    int i = blockIdx.x * blockDim.x + threadIdx.x;
    if (i >= K * HID) return;
    int k = i / HID, n = i % HID;
    float v = W[i];
    __nv_bfloat16 h = __float2bfloat16(v);
    __nv_bfloat16 l = __float2bfloat16(v - __bfloat162float(h));
    Bh[(size_t)n * K + k] = h;
    Bl[(size_t)n * K + k] = l;
}

// ---------------- HMMA GEMM (BM=128, double-buffered, cp.async) ------------
__global__ void __launch_bounds__(256, 2)
hmma_gemm(const float *__restrict__ A,
          const __nv_bfloat16 *__restrict__ Bhg,
          const __nv_bfloat16 *__restrict__ Blg,
          const float *__restrict__ bias, const float *__restrict__ dinv,
          float *__restrict__ C, int M, int K)
{
    extern __shared__ __align__(1024) char smem[];
    const uint32_t sb = s2u(smem);
    const int tid = threadIdx.x;
    const int wid = tid >> 5, lane = tid & 31;
    const int warp_m = wid & 3, warp_n = wid >> 2;
    const int bm0 = blockIdx.x * 128;

    const int alr = tid >> 1, alq = tid & 1;
    int arow = bm0 + alr; if (arow >= M) arow = M - 1;
    const float *Ar = A + (size_t)arow * K + alq * 16;
    const uint32_t a_sts = (uint32_t)(alr * ASTRIDE + alq * 32);

    const int bln = tid >> 1, blu = tid & 1;
    const __nv_bfloat16 *Bhr = Bhg + (size_t)bln * K + blu * 16;
    const __nv_bfloat16 *Blr = Blg + (size_t)bln * K + blu * 16;
    const uint32_t b_sts = (uint32_t)(bln * ASTRIDE + blu * 32);

    const int sub = lane >> 3, lr8 = lane & 7;
    uint32_t a_off[2], b_off[4];
#pragma unroll
    for (int mi = 0; mi < 2; ++mi) {
        int row = warp_m * 32 + mi * 16 + ((sub & 1) << 3) + lr8;
        a_off[mi] = (uint32_t)(row * ASTRIDE + ((sub >> 1) << 4));
    }
#pragma unroll
    for (int np = 0; np < 4; ++np) {
        int nr = warp_n * 64 + np * 16 + ((sub >> 1) << 3) + lr8;
        b_off[np] = (uint32_t)(nr * ASTRIDE + ((sub & 1) << 4));
    }

    float acc[2][8][4];
#pragma unroll
    for (int mi = 0; mi < 2; ++mi)
#pragma unroll
        for (int ni = 0; ni < 8; ++ni)
#pragma unroll
            for (int q = 0; q < 4; ++q) acc[mi][ni][q] = 0.f;

    const int NC = K / BK;
    float4 va0, va1, va2, va3;

    // ---- prologue ----
    va0 = *(const float4 *)(Ar);
    va1 = *(const float4 *)(Ar + 4);
    va2 = *(const float4 *)(Ar + 8);
    va3 = *(const float4 *)(Ar + 12);
    {
        uint32_t s0 = sb + 2 * ABUF + b_sts;
        cpa16(s0,             Bhr);
        cpa16(s0 + 16,        Bhr + 8);
        cpa16(s0 + BBUF,      Blr);
        cpa16(s0 + BBUF + 16, Blr + 8);
        asm volatile("cp.async.commit_group;" ::: "memory");
    }
    {
        uint4 hv, lv;
        cvt8(va0, va1, hv, lv);
        *(uint4 *)(smem + a_sts)        = hv;
        *(uint4 *)(smem + ABUF + a_sts) = lv;
        cvt8(va2, va3, hv, lv);
        *(uint4 *)(smem + a_sts + 16)        = hv;
        *(uint4 *)(smem + ABUF + a_sts + 16) = lv;
    }
    asm volatile("cp.async.wait_group 0;" ::: "memory");
    __syncthreads();

    for (int c = 0; c < NC; ++c) {
        const uint32_t bo = (c & 1) ? (uint32_t)BUFSZ : 0u;
        const uint32_t bn = (c & 1) ? 0u : (uint32_t)BUFSZ;
        const bool more = (c + 1 < NC);
        if (more) {
            const int k1 = (c + 1) * BK;
            va0 = *(const float4 *)(Ar + k1);
            va1 = *(const float4 *)(Ar + k1 + 4);
            va2 = *(const float4 *)(Ar + k1 + 8);
            va3 = *(const float4 *)(Ar + k1 + 12);
            uint32_t s0 = sb + bn + 2 * ABUF + b_sts;
            cpa16(s0,             Bhr + k1);
            cpa16(s0 + 16,        Bhr + k1 + 8);
            cpa16(s0 + BBUF,      Blr + k1);
            cpa16(s0 + BBUF + 16, Blr + k1 + 8);
            asm volatile("cp.async.commit_group;" ::: "memory");
        }

#pragma unroll
        for (int ks = 0; ks < 2; ++ks) {
            uint32_t ahi[2][4], alo[2][4];
#pragma unroll
            for (int mi = 0; mi < 2; ++mi) {
                uint32_t ad = sb + bo + a_off[mi] + ks * 32;
                ldsm4(ahi[mi][0], ahi[mi][1], ahi[mi][2], ahi[mi][3], ad);
                ldsm4(alo[mi][0], alo[mi][1], alo[mi][2], alo[mi][3], ad + ABUF);
            }
#pragma unroll
            for (int np = 0; np < 4; ++np) {
                uint32_t bhi[2][2], blo[2][2];
                uint32_t bd = sb + bo + 2 * ABUF + b_off[np] + ks * 32;
                ldsm4(bhi[0][0], bhi[0][1], bhi[1][0], bhi[1][1], bd);
                ldsm4(blo[0][0], blo[0][1], blo[1][0], blo[1][1], bd + BBUF);
#pragma unroll
                for (int mi = 0; mi < 2; ++mi)
#pragma unroll
                    for (int h = 0; h < 2; ++h)
                        mma16816(acc[mi][np * 2 + h], ahi[mi], bhi[h]);
#pragma unroll
                for (int mi = 0; mi < 2; ++mi)
#pragma unroll
                    for (int h = 0; h < 2; ++h)
                        mma16816(acc[mi][np * 2 + h], ahi[mi], blo[h]);
#pragma unroll
                for (int mi = 0; mi < 2; ++mi)
#pragma unroll
                    for (int h = 0; h < 2; ++h)
                        mma16816(acc[mi][np * 2 + h], alo[mi], bhi[h]);
            }
        }

        if (more) {
            uint4 hv, lv;
            cvt8(va0, va1, hv, lv);
            *(uint4 *)(smem + bn + a_sts)        = hv;
            *(uint4 *)(smem + bn + ABUF + a_sts) = lv;
            cvt8(va2, va3, hv, lv);
            *(uint4 *)(smem + bn + a_sts + 16)        = hv;
            *(uint4 *)(smem + bn + ABUF + a_sts + 16) = lv;
            asm volatile("cp.async.wait_group 0;" ::: "memory");
        }
        __syncthreads();
    }

    // ---- epilogue ----
    const int gid = lane >> 2, qid = lane & 3;
#pragma unroll
    for (int mi = 0; mi < 2; ++mi) {
        int row0 = bm0 + warp_m * 32 + mi * 16 + gid;
        int row1 = row0 + 8;
        float s0 = 1.f, s1 = 1.f;
        if (dinv) {
            if (row0 < M) s0 = dinv[row0];
            if (row1 < M) s1 = dinv[row1];
        }
#pragma unroll
        for (int ni = 0; ni < 8; ++ni) {
            int col = warp_n * 64 + ni * 8 + qid * 2;
            float b0 = 0.f, b1 = 0.f;
            if (bias) { b0 = bias[col]; b1 = bias[col + 1]; }
            if (row0 < M) {
                float2 o = make_float2(fmaf(acc[mi][ni][0], s0, b0),
                                       fmaf(acc[mi][ni][1], s0, b1));
                *(float2 *)&C[(size_t)row0 * HID + col] = o;
            }
            if (row1 < M) {
                float2 o = make_float2(fmaf(acc[mi][ni][2], s1, b0),
                                       fmaf(acc[mi][ni][3], s1, b1));
                *(float2 *)&C[(size_t)row1 * HID + col] = o;
            }
        }
    }
}

// ---------------- CSR aggregate: warp per node -----------------------------
// mode 0: out = relu?(dinv*(agg+self)+bias)  -> outp
// mode 1: o = dinv*(agg+self)+bias, red4 into pool[batch[node]] (+count)
__global__ void __launch_bounds__(256)
k_agg(const float *__restrict__ hs, const float *__restrict__ bias,
      float *__restrict__ outp, const int *__restrict__ batch,
      float *__restrict__ pool, int relu, int pool_mode, int N)
{
    int node = (blockIdx.x * blockDim.x + threadIdx.x) >> 5;
    if (node >= N) return;
    int lane = threadIdx.x & 31;
    int c = lane * 4;

    int e0 = g_start[node], e1 = g_start[node + 1];
    float4 acc = *(const float4 *)&hs[(size_t)node * HID + c];

    int e = e0;
    for (; e + 4 <= e1; e += 4) {
        int i0 = g_csr[e], i1 = g_csr[e + 1], i2 = g_csr[e + 2], i3 = g_csr[e + 3];
        float4 v0 = *(const float4 *)&hs[(size_t)i0 * HID + c];
        float4 v1 = *(const float4 *)&hs[(size_t)i1 * HID + c];
        float4 v2 = *(const float4 *)&hs[(size_t)i2 * HID + c];
        float4 v3 = *(const float4 *)&hs[(size_t)i3 * HID + c];
        acc.x += v0.x + v1.x + v2.x + v3.x;
        acc.y += v0.y + v1.y + v2.y + v3.y;
        acc.z += v0.z + v1.z + v2.z + v3.z;
        acc.w += v0.w + v1.w + v2.w + v3.w;
    }
    for (; e < e1; ++e) {
        int i0 = g_csr[e];
        float4 v0 = *(const float4 *)&hs[(size_t)i0 * HID + c];
        acc.x += v0.x; acc.y += v0.y; acc.z += v0.z; acc.w += v0.w;
    }

    float dv = g_dinv[node];
    float4 b = *(const float4 *)&bias[c];
    float4 o;
    o.x = fmaf(dv, acc.x, b.x);
    o.y = fmaf(dv, acc.y, b.y);
    o.z = fmaf(dv, acc.z, b.z);
    o.w = fmaf(dv, acc.w, b.w);
    if (relu) {
        o.x = fmaxf(o.x, 0.f); o.y = fmaxf(o.y, 0.f);
        o.z = fmaxf(o.z, 0.f); o.w = fmaxf(o.w, 0.f);
    }
    if (pool_mode) {
        int g = batch[node];
        red4(&pool[(size_t)g * HID + c], o);
        if (lane == 0) atomicAdd(&pool[NGRAPH * HID + g], 1.0f);
    } else {
        *(float4 *)&outp[(size_t)node * HID + c] = o;
    }
}

// ---------------- head MLP: block per graph --------------------------------
__global__ void k_head(const float *__restrict__ pool,
                       const float *__restrict__ W1, const float *__restrict__ b1,
                       const float *__restrict__ W2, const float *__restrict__ b2,
                       float *__restrict__ out)
{
    __shared__ float gv[HID];
    __shared__ float hid[HID];
    int g = blockIdx.x, t = threadIdx.x;
    float cnt = fmaxf(pool[NGRAPH * HID + g], 1.0f);
    gv[t] = pool[(size_t)g * HID + t] / cnt;
    __syncthreads();
    float acc = b1[t];
#pragma unroll 8
    for (int c = 0; c < HID; ++c) acc = fmaf(gv[c], W1[c * HID + t], acc);
    hid[t] = fmaxf(acc, 0.f);
    __syncthreads();
    if (t < NCLS) {
        float o = b2[t];
#pragma unroll 8
        for (int hh = 0; hh < HID; ++hh) o = fmaf(hid[hh], W2[hh * NCLS + t], o);
        out[g * NCLS + t] = o;
    }
}

// ---------------- launcher -------------------------------------------------
extern "C" void kernel_launch(void *const *d_in, const int *in_sizes, int n_in,
                              void *d_out, int out_size)
{
    const float *x     = (const float *)d_in[0];
    const int   *ei    = (const int *)d_in[1];
    const int   *batch = (const int *)d_in[2];
    const float *W_emb = (const float *)d_in[3], *b_emb = (const float *)d_in[4];
    const float *W_c1  = (const float *)d_in[5], *b_c1  = (const float *)d_in[6];
    const float *W_c2  = (const float *)d_in[7], *b_c2  = (const float *)d_in[8];
    const float *W_l1  = (const float *)d_in[9], *b_l1  = (const float *)d_in[10];
    const float *W_l2  = (const float *)d_in[11], *b_l2 = (const float *)d_in[12];
    float *out = (float *)d_out;

    const int E = in_sizes[1] / 2;
    const int N = in_sizes[2];
    const int K_IN = in_sizes[0] / N;

    static float *p_h = nullptr, *p_hs = nullptr, *p_dinv = nullptr,
                 *p_pool = nullptr;
    static int *p_deg = nullptr;
    static __nv_bfloat16 *p_We_h, *p_We_l, *p_W1_h, *p_W1_l, *p_W2_h, *p_W2_l;
    static cudaStream_t s2 = nullptr;
    static cudaEvent_t evFork = nullptr, evJoin = nullptr;
    if (!p_h) {
        cudaGetSymbolAddress((void **)&p_h,    g_h);
        cudaGetSymbolAddress((void **)&p_hs,   g_hs);
        cudaGetSymbolAddress((void **)&p_dinv, g_dinv);
        cudaGetSymbolAddress((void **)&p_pool, g_pool);
        cudaGetSymbolAddress((void **)&p_deg,  g_deg);
        cudaGetSymbolAddress((void **)&p_We_h, g_Wemb_h);
        cudaGetSymbolAddress((void **)&p_We_l, g_Wemb_l);
        cudaGetSymbolAddress((void **)&p_W1_h, g_Wc1_h);
        cudaGetSymbolAddress((void **)&p_W1_l, g_Wc1_l);
        cudaGetSymbolAddress((void **)&p_W2_h, g_Wc2_h);
        cudaGetSymbolAddress((void **)&p_W2_l, g_Wc2_l);
        cudaFuncSetAttribute(hmma_gemm,
                             cudaFuncAttributeMaxDynamicSharedMemorySize, MMA_SMEM);
        cudaStreamCreateWithFlags(&s2, cudaStreamNonBlocking);
        cudaEventCreateWithFlags(&evFork, cudaEventDisableTiming);
        cudaEventCreateWithFlags(&evJoin, cudaEventDisableTiming);
    }

    const int mma_grid  = (N + 127) / 128;
    const int agg_grid  = (N * 32 + 255) / 256;

    // ---- fork: side chain on s2 (independent of GEMM1) ----
    cudaEventRecord(evFork, 0);
    cudaStreamWaitEvent(s2, evFork, 0);

    k_zero_deg<<<(N + 255) / 256, 256, 0, s2>>>(p_deg, N);
    k_deg <<<(E + 255) / 256, 256, 0, s2>>>(ei, E);
    k_dinv<<<(N + 255) / 256, 256, 0, s2>>>(N);
    k_scan1<<<NSCANB, 256, 0, s2>>>(N);
    k_scan2<<<1, 256, 0, s2>>>();
    k_scan3<<<(N + 255) / 256, 256, 0, s2>>>(N, E);
    k_fill <<<(E + 255) / 256, 256, 0, s2>>>(ei, E);
    k_prepW<<<(HID * HID + 255) / 256, 256, 0, s2>>>(W_c1, p_W1_h, p_W1_l, HID);
    k_prepW<<<(HID * HID + 255) / 256, 256, 0, s2>>>(W_c2, p_W2_h, p_W2_l, HID);
    k_zero4<<<(NGRAPH * (HID + 1) / 4 + 255) / 256, 256, 0, s2>>>(
        (float4 *)p_pool, NGRAPH * (HID + 1) / 4);

    // main chain: embedding GEMM
    k_prepW<<<(K_IN * HID + 255) / 256, 256>>>(W_emb, p_We_h, p_We_l, K_IN);
    hmma_gemm<<<mma_grid, 256, MMA_SMEM>>>(x, p_We_h, p_We_l, b_emb, nullptr,
                                           p_h, N, K_IN);

    // ---- join ----
    cudaEventRecord(evJoin, s2);
    cudaStreamWaitEvent(0, evJoin, 0);

    // conv1: hs = dinv*(h0@Wc1); h1 = relu(dinv*(agg+self)+b)
    hmma_gemm<<<mma_grid, 256, MMA_SMEM>>>(p_h, p_W1_h, p_W1_l, nullptr, p_dinv,
                                           p_hs, N, HID);
    k_agg<<<agg_grid, 256>>>(p_hs, b_c1, p_h, nullptr, nullptr, 1, 0, N);

    // conv2: hs = dinv*(h1@Wc2); fused agg + global-mean-pool accumulation
    hmma_gemm<<<mma_grid, 256, MMA_SMEM>>>(p_h, p_W2_h, p_W2_l, nullptr, p_dinv,
                                           p_hs, N, HID);
    k_agg<<<agg_grid, 256>>>(p_hs, b_c2, nullptr, batch, p_pool, 0, 1, N);

    // head
    k_head<<<NGRAPH, HID>>>(p_pool, W_l1, b_l1, W_l2, b_l2, out);
}